// round 1
// baseline (speedup 1.0000x reference)
#include <cuda_runtime.h>
#include <cuda_bf16.h>
#include <cstdint>

// Problem constants
#define NBATCH   16384
#define NAG      32
#define NOBS     64
#define NH       64
#define NACT     16
#define NROUNDS  2

// Tiling
#define ROWS     128          // rows per CTA = 4 batches of 32 agents
#define NTHREADS 256          // 8 warps, each owns a 16-row stripe

// SMEM strides (bf16 elements); +8 pad -> 16B offset per row mod 128B, conflict-free LDSM
#define SA_STRIDE 136         // activation tile rows: 128 cols (h | msg) + 8 pad
#define W_STRIDE  72          // 64-col weight rows + 8 pad
#define W2_STRIDE 24          // 16-col weight rows + 8 pad

#define SMEM_BYTES 95296

// ---------------------------------------------------------------------------
// Pre-converted bf16 weights (written by prologue kernel each launch)
// ---------------------------------------------------------------------------
__device__ __nv_bfloat16 g_enc_w [NOBS * NH];
__device__ __nv_bfloat16 g_comm_w[NROUNDS * 2 * NH * NH];
__device__ __nv_bfloat16 g_out_w1[NH * NH];
__device__ __nv_bfloat16 g_out_w2[NH * NACT];

__global__ void convert_weights_kernel(const float* __restrict__ enc_w,
                                       const float* __restrict__ comm_w,
                                       const float* __restrict__ out_w1,
                                       const float* __restrict__ out_w2) {
    int i = blockIdx.x * blockDim.x + threadIdx.x;
    if (i < NOBS * NH)                 g_enc_w[i]  = __float2bfloat16(enc_w[i]);
    if (i < NROUNDS * 2 * NH * NH)     g_comm_w[i] = __float2bfloat16(comm_w[i]);
    if (i < NH * NH)                   g_out_w1[i] = __float2bfloat16(out_w1[i]);
    if (i < NH * NACT)                 g_out_w2[i] = __float2bfloat16(out_w2[i]);
}

// ---------------------------------------------------------------------------
// PTX helpers
// ---------------------------------------------------------------------------
__device__ __forceinline__ uint32_t smem_u32(const void* p) {
    return (uint32_t)__cvta_generic_to_shared(p);
}

__device__ __forceinline__ void ldsm_x4(uint32_t& r0, uint32_t& r1, uint32_t& r2, uint32_t& r3, uint32_t a) {
    asm volatile("ldmatrix.sync.aligned.m8n8.x4.shared.b16 {%0,%1,%2,%3}, [%4];"
                 : "=r"(r0), "=r"(r1), "=r"(r2), "=r"(r3) : "r"(a));
}

__device__ __forceinline__ void ldsm_x4_t(uint32_t& r0, uint32_t& r1, uint32_t& r2, uint32_t& r3, uint32_t a) {
    asm volatile("ldmatrix.sync.aligned.m8n8.x4.trans.shared.b16 {%0,%1,%2,%3}, [%4];"
                 : "=r"(r0), "=r"(r1), "=r"(r2), "=r"(r3) : "r"(a));
}

__device__ __forceinline__ void mma16816(float* c,
                                         uint32_t a0, uint32_t a1, uint32_t a2, uint32_t a3,
                                         uint32_t b0, uint32_t b1) {
    asm volatile("mma.sync.aligned.m16n8k16.row.col.f32.bf16.bf16.f32 "
                 "{%0,%1,%2,%3}, {%4,%5,%6,%7}, {%8,%9}, {%0,%1,%2,%3};"
                 : "+f"(c[0]), "+f"(c[1]), "+f"(c[2]), "+f"(c[3])
                 : "r"(a0), "r"(a1), "r"(a2), "r"(a3), "r"(b0), "r"(b1));
}

// C[16][8*NT] = A[16][K] * W[K][8*NT], A rows = warp stripe in sA (row-major bf16),
// W row-major [K][cols] bf16 in smem. Fully unrolled.
template <int K, int NT>
__device__ __forceinline__ void warp_gemm(const __nv_bfloat16* sA, int m0,
                                          const __nv_bfloat16* sW, int wstride,
                                          float acc[][4], int lane) {
#pragma unroll
    for (int nt = 0; nt < NT; ++nt) {
        acc[nt][0] = 0.f; acc[nt][1] = 0.f; acc[nt][2] = 0.f; acc[nt][3] = 0.f;
    }
#pragma unroll
    for (int k0 = 0; k0 < K; k0 += 16) {
        uint32_t a0, a1, a2, a3;
        // lanes 0..15 -> rows m0..m0+15 at col k0; lanes 16..31 -> same rows at col k0+8
        ldsm_x4(a0, a1, a2, a3,
                smem_u32(sA + (m0 + (lane & 15)) * SA_STRIDE + k0 + ((lane >> 4) << 3)));
#pragma unroll
        for (int nt = 0; nt < NT; nt += 2) {
            uint32_t b0, b1, b2, b3;
            // trans-load: rows k0+(lane&15), cols nt*8 + (lane>>4)*8 -> B frags for 2 n-tiles
            ldsm_x4_t(b0, b1, b2, b3,
                      smem_u32(sW + (k0 + (lane & 15)) * wstride + nt * 8 + ((lane >> 4) << 3)));
            mma16816(acc[nt],     a0, a1, a2, a3, b0, b1);
            mma16816(acc[nt + 1], a0, a1, a2, a3, b2, b3);
        }
    }
}

// bias + relu + bf16, store into sA[., 0..63] (own warp rows only -> no cross-warp hazard)
__device__ __forceinline__ void store_h(__nv_bfloat16* sA, int m0, int lane,
                                        float acc[][4], const float* sBias) {
    int row  = m0 + (lane >> 2);
    int colb = (lane & 3) * 2;
#pragma unroll
    for (int nt = 0; nt < 8; ++nt) {
        int col  = nt * 8 + colb;
        float b0 = sBias[col], b1 = sBias[col + 1];
        float v0 = fmaxf(acc[nt][0] + b0, 0.f);
        float v1 = fmaxf(acc[nt][1] + b1, 0.f);
        float v2 = fmaxf(acc[nt][2] + b0, 0.f);
        float v3 = fmaxf(acc[nt][3] + b1, 0.f);
        *(__nv_bfloat162*)(sA + row * SA_STRIDE + col)       = __floats2bfloat162_rn(v0, v1);
        *(__nv_bfloat162*)(sA + (row + 8) * SA_STRIDE + col) = __floats2bfloat162_rn(v2, v3);
    }
}

// ---------------------------------------------------------------------------
// Fused CommNet kernel: 1 CTA = 4 batches (128 rows), whole pipeline in SMEM
// ---------------------------------------------------------------------------
__global__ void __launch_bounds__(NTHREADS, 1)
commnet_kernel(const float* __restrict__ obs,
               const float* __restrict__ enc_b,
               const float* __restrict__ comm_b,
               const float* __restrict__ out_b1,
               const float* __restrict__ out_b2,
               const int*   __restrict__ avail,
               float*       __restrict__ out) {
    extern __shared__ __align__(16) char smem_raw[];
    __nv_bfloat16* sA   = (__nv_bfloat16*)smem_raw;                 // 128 x 136
    __nv_bfloat16* sWe  = sA   + ROWS * SA_STRIDE;                  // 64  x 72
    __nv_bfloat16* sWc  = sWe  + NH * W_STRIDE;                     // 256 x 72 (2 rounds x 128)
    __nv_bfloat16* sWo1 = sWc  + NROUNDS * 2 * NH * W_STRIDE;       // 64  x 72
    __nv_bfloat16* sWo2 = sWo1 + NH * W_STRIDE;                     // 64  x 24
    float* sColsum = (float*)(sWo2 + NH * W2_STRIDE);               // 4 x 64
    float* sBias   = sColsum + 4 * NH;                              // 272 floats

    const int tid  = threadIdx.x;
    const int lane = tid & 31;
    const int warp = tid >> 5;
    const int m0   = warp * 16;
    const long long row0 = (long long)blockIdx.x * ROWS;

    // ---- stage obs tile -> sA[., 0..63] as bf16 ----
    const float4* gobs = (const float4*)(obs + (size_t)row0 * NOBS);
    for (int i = tid; i < ROWS * NOBS / 4; i += NTHREADS) {
        int r  = i >> 4;          // NOBS/4 = 16 float4 per row
        int c4 = (i & 15) * 4;
        float4 v = gobs[i];
        __nv_bfloat162 p0 = __floats2bfloat162_rn(v.x, v.y);
        __nv_bfloat162 p1 = __floats2bfloat162_rn(v.z, v.w);
        uint2 st;
        st.x = *(uint32_t*)&p0;
        st.y = *(uint32_t*)&p1;
        *(uint2*)(sA + r * SA_STRIDE + c4) = st;
    }
    // ---- stage weights (bf16, L2-resident) ----
    for (int i = tid; i < NH * NH / 4; i += NTHREADS) {
        int r = i >> 4, c4 = (i & 15) * 4;
        *(uint2*)(sWe + r * W_STRIDE + c4) = *(const uint2*)(g_enc_w + r * NH + c4);
    }
    for (int i = tid; i < NROUNDS * 2 * NH * NH / 4; i += NTHREADS) {
        int r = i >> 4, c4 = (i & 15) * 4;
        *(uint2*)(sWc + r * W_STRIDE + c4) = *(const uint2*)(g_comm_w + r * NH + c4);
    }
    for (int i = tid; i < NH * NH / 4; i += NTHREADS) {
        int r = i >> 4, c4 = (i & 15) * 4;
        *(uint2*)(sWo1 + r * W_STRIDE + c4) = *(const uint2*)(g_out_w1 + r * NH + c4);
    }
    for (int i = tid; i < NH * NACT / 4; i += NTHREADS) {
        int r = i >> 2, c4 = (i & 3) * 4;
        *(uint2*)(sWo2 + r * W2_STRIDE + c4) = *(const uint2*)(g_out_w2 + r * NACT + c4);
    }
    if (tid < 64)  sBias[tid]        = enc_b[tid];
    if (tid < 128) sBias[64 + tid]   = comm_b[tid];
    if (tid < 64)  sBias[192 + tid]  = out_b1[tid];
    if (tid < 16)  sBias[256 + tid]  = out_b2[tid];
    __syncthreads();

    float acc[8][4];

    // ---- encoder: h = relu(obs @ enc_w + enc_b) ----
    warp_gemm<64, 8>(sA, m0, sWe, W_STRIDE, acc, lane);
    store_h(sA, m0, lane, acc, sBias);

    // ---- comm rounds ----
#pragma unroll
    for (int rd = 0; rd < NROUNDS; ++rd) {
        __syncthreads();
        // per-batch column sums over 32 agents (fp32)
        {
            int b = tid >> 6, c = tid & 63;
            float s = 0.f;
            const __nv_bfloat16* p = sA + (b * NAG) * SA_STRIDE + c;
#pragma unroll
            for (int r = 0; r < NAG; ++r) s += __bfloat162float(p[r * SA_STRIDE]);
            sColsum[(b << 6) + c] = s;
        }
        __syncthreads();
        // msg = (sum - h) / (N-1) -> sA[., 64..127]
        for (int i = tid; i < ROWS * NH; i += NTHREADS) {
            int row = i >> 6, col = i & 63;
            float hv  = __bfloat162float(sA[row * SA_STRIDE + col]);
            float msg = (sColsum[((row >> 5) << 6) + col] - hv) * (1.0f / 31.0f);
            sA[row * SA_STRIDE + 64 + col] = __float2bfloat16(msg);
        }
        __syncthreads();
        // h = relu([h | msg] @ comm_w[rd] + comm_b[rd])
        warp_gemm<128, 8>(sA, m0, sWc + rd * 2 * NH * W_STRIDE, W_STRIDE, acc, lane);
        store_h(sA, m0, lane, acc, sBias + 64 + rd * 64);
    }

    // ---- out1: hid = relu(h @ out_w1 + out_b1) (own rows only, no sync needed) ----
    warp_gemm<64, 8>(sA, m0, sWo1, W_STRIDE, acc, lane);
    store_h(sA, m0, lane, acc, sBias + 192);

    // ---- out2: q = hid @ out_w2 + out_b2, mask, write gmem ----
    float acc2[2][4];
    warp_gemm<64, 2>(sA, m0, sWo2, W2_STRIDE, acc2, lane);
    {
        int r    = lane >> 2;
        int colb = (lane & 3) * 2;
#pragma unroll
        for (int nt = 0; nt < 2; ++nt) {
            int col  = nt * 8 + colb;
            float b0 = sBias[256 + col], b1 = sBias[256 + col + 1];
#pragma unroll
            for (int half = 0; half < 2; ++half) {
                long long grow = row0 + m0 + r + half * 8;
                int2 av = *(const int2*)(avail + grow * NACT + col);
                float q0 = acc2[nt][half * 2 + 0] + b0;
                float q1 = acc2[nt][half * 2 + 1] + b1;
                if (av.x == 0) q0 = -1e10f;
                if (av.y == 0) q1 = -1e10f;
                *(float2*)(out + grow * NACT + col) = make_float2(q0, q1);
            }
        }
    }
}

// ---------------------------------------------------------------------------
extern "C" void kernel_launch(void* const* d_in, const int* in_sizes, int n_in,
                              void* d_out, int out_size) {
    const float* obs    = (const float*)d_in[0];
    const float* enc_w  = (const float*)d_in[1];
    const float* enc_b  = (const float*)d_in[2];
    const float* comm_w = (const float*)d_in[3];
    const float* comm_b = (const float*)d_in[4];
    const float* out_w1 = (const float*)d_in[5];
    const float* out_b1 = (const float*)d_in[6];
    const float* out_w2 = (const float*)d_in[7];
    const float* out_b2 = (const float*)d_in[8];
    const int*   avail  = (const int*)d_in[9];
    float* out = (float*)d_out;

    cudaFuncSetAttribute(commnet_kernel, cudaFuncAttributeMaxDynamicSharedMemorySize, SMEM_BYTES);

    // weights -> bf16 (16384 = max array size, exactly 64*256 threads)
    convert_weights_kernel<<<64, 256>>>(enc_w, comm_w, out_w1, out_w2);

    commnet_kernel<<<(NBATCH * NAG) / ROWS, NTHREADS, SMEM_BYTES>>>(
        obs, enc_b, comm_b, out_b1, out_b2, avail, out);
}

// round 2
// speedup vs baseline: 1.6398x; 1.6398x over previous
#include <cuda_runtime.h>
#include <cuda_bf16.h>
#include <cstdint>

// Problem constants
#define NBATCH   16384
#define NAG      32
#define NOBS     64
#define NH       64
#define NACT     16
#define NROUNDS  2

// Tiling
#define ROWS     128          // rows per tile = 4 batches of 32 agents
#define NTILES   ((NBATCH * NAG) / ROWS)   // 4096
#define NTHREADS 256          // 8 warps, each owns a 16-row stripe
#define NCTAS    152          // persistent: 1 CTA per SM on GB300

// SMEM strides; pads chosen for conflict-free LDSM (16B shift per row pattern)
#define SA_STRIDE 136         // activation rows: 128 bf16 cols (h | msg) + 8 pad
#define OBS_STRIDE 68         // fp32 obs staging rows: 64 + 4 pad (272B, 16B-aligned)
#define W_STRIDE  72          // 64-col weight rows + 8 pad
#define W2_STRIDE 24          // 16-col weight rows + 8 pad

// ---------------------------------------------------------------------------
// Globals: bf16 weights (prologue-converted) + persistent work counter
// ---------------------------------------------------------------------------
__device__ __nv_bfloat16 g_enc_w [NOBS * NH];
__device__ __nv_bfloat16 g_comm_w[NROUNDS * 2 * NH * NH];
__device__ __nv_bfloat16 g_out_w1[NH * NH];
__device__ __nv_bfloat16 g_out_w2[NH * NACT];
__device__ unsigned      g_tile_ctr;

__global__ void convert_weights_kernel(const float* __restrict__ enc_w,
                                       const float* __restrict__ comm_w,
                                       const float* __restrict__ out_w1,
                                       const float* __restrict__ out_w2) {
    int i = blockIdx.x * blockDim.x + threadIdx.x;
    if (i == 0) g_tile_ctr = 0;
    if (i < NOBS * NH)                 g_enc_w[i]  = __float2bfloat16(enc_w[i]);
    if (i < NROUNDS * 2 * NH * NH)     g_comm_w[i] = __float2bfloat16(comm_w[i]);
    if (i < NH * NH)                   g_out_w1[i] = __float2bfloat16(out_w1[i]);
    if (i < NH * NACT)                 g_out_w2[i] = __float2bfloat16(out_w2[i]);
}

// ---------------------------------------------------------------------------
// PTX helpers
// ---------------------------------------------------------------------------
__device__ __forceinline__ uint32_t smem_u32(const void* p) {
    return (uint32_t)__cvta_generic_to_shared(p);
}
__device__ __forceinline__ void cp16(void* dst, const void* src) {
    asm volatile("cp.async.cg.shared.global [%0], [%1], 16;"
                 :: "r"(smem_u32(dst)), "l"(src));
}
__device__ __forceinline__ void cp_commit() { asm volatile("cp.async.commit_group;"); }
__device__ __forceinline__ void cp_wait_all() { asm volatile("cp.async.wait_group 0;"); }

__device__ __forceinline__ void ldsm_x4(uint32_t& r0, uint32_t& r1, uint32_t& r2, uint32_t& r3, uint32_t a) {
    asm volatile("ldmatrix.sync.aligned.m8n8.x4.shared.b16 {%0,%1,%2,%3}, [%4];"
                 : "=r"(r0), "=r"(r1), "=r"(r2), "=r"(r3) : "r"(a));
}
__device__ __forceinline__ void ldsm_x4_t(uint32_t& r0, uint32_t& r1, uint32_t& r2, uint32_t& r3, uint32_t a) {
    asm volatile("ldmatrix.sync.aligned.m8n8.x4.trans.shared.b16 {%0,%1,%2,%3}, [%4];"
                 : "=r"(r0), "=r"(r1), "=r"(r2), "=r"(r3) : "r"(a));
}
__device__ __forceinline__ void mma16816(float* c,
                                         uint32_t a0, uint32_t a1, uint32_t a2, uint32_t a3,
                                         uint32_t b0, uint32_t b1) {
    asm volatile("mma.sync.aligned.m16n8k16.row.col.f32.bf16.bf16.f32 "
                 "{%0,%1,%2,%3}, {%4,%5,%6,%7}, {%8,%9}, {%0,%1,%2,%3};"
                 : "+f"(c[0]), "+f"(c[1]), "+f"(c[2]), "+f"(c[3])
                 : "r"(a0), "r"(a1), "r"(a2), "r"(a3), "r"(b0), "r"(b1));
}

// C[16][8*NT] = A[16][K] @ W[K][8*NT]
template <int K, int NT>
__device__ __forceinline__ void warp_gemm(const __nv_bfloat16* sA, int m0,
                                          const __nv_bfloat16* sW, int wstride,
                                          float acc[][4], int lane) {
#pragma unroll
    for (int nt = 0; nt < NT; ++nt) {
        acc[nt][0] = 0.f; acc[nt][1] = 0.f; acc[nt][2] = 0.f; acc[nt][3] = 0.f;
    }
#pragma unroll
    for (int k0 = 0; k0 < K; k0 += 16) {
        uint32_t a0, a1, a2, a3;
        ldsm_x4(a0, a1, a2, a3,
                smem_u32(sA + (m0 + (lane & 15)) * SA_STRIDE + k0 + ((lane >> 4) << 3)));
#pragma unroll
        for (int nt = 0; nt < NT; nt += 2) {
            uint32_t b0, b1, b2, b3;
            ldsm_x4_t(b0, b1, b2, b3,
                      smem_u32(sW + (k0 + (lane & 15)) * wstride + nt * 8 + ((lane >> 4) << 3)));
            mma16816(acc[nt],     a0, a1, a2, a3, b0, b1);
            mma16816(acc[nt + 1], a0, a1, a2, a3, b2, b3);
        }
    }
}

// bias + relu + bf16 -> sA[own rows, 0..63]
__device__ __forceinline__ void store_h(__nv_bfloat16* sA, int m0, int lane,
                                        float acc[][4], const float* sBias) {
    int row  = m0 + (lane >> 2);
    int colb = (lane & 3) * 2;
#pragma unroll
    for (int nt = 0; nt < 8; ++nt) {
        int col  = nt * 8 + colb;
        float b0 = sBias[col], b1 = sBias[col + 1];
        float v0 = fmaxf(acc[nt][0] + b0, 0.f);
        float v1 = fmaxf(acc[nt][1] + b1, 0.f);
        float v2 = fmaxf(acc[nt][2] + b0, 0.f);
        float v3 = fmaxf(acc[nt][3] + b1, 0.f);
        *(__nv_bfloat162*)(sA + row * SA_STRIDE + col)       = __floats2bfloat162_rn(v0, v1);
        *(__nv_bfloat162*)(sA + (row + 8) * SA_STRIDE + col) = __floats2bfloat162_rn(v2, v3);
    }
}

// ---------------------------------------------------------------------------
// Persistent fused CommNet kernel
// ---------------------------------------------------------------------------
__global__ void __launch_bounds__(NTHREADS, 1)
commnet_kernel(const float* __restrict__ obs,
               const float* __restrict__ enc_b,
               const float* __restrict__ comm_b,
               const float* __restrict__ out_b1,
               const float* __restrict__ out_b2,
               const int*   __restrict__ avail,
               float*       __restrict__ out) {
    extern __shared__ __align__(16) char smem_raw[];
    __nv_bfloat16* sA     = (__nv_bfloat16*)smem_raw;                // 128 x 136   34816 B
    float*         sObs   = (float*)(sA + ROWS * SA_STRIDE);         // 128 x 68    34816 B
    int*           sAvail = (int*)(sObs + ROWS * OBS_STRIDE);        // 2 x 128x16  16384 B
    __nv_bfloat16* sWe    = (__nv_bfloat16*)(sAvail + 2 * ROWS * NACT); // 64 x 72   9216 B
    __nv_bfloat16* sWc    = sWe  + NH * W_STRIDE;                    // 256 x 72   36864 B
    __nv_bfloat16* sWo1   = sWc  + NROUNDS * 2 * NH * W_STRIDE;      // 64 x 72     9216 B
    __nv_bfloat16* sWo2   = sWo1 + NH * W_STRIDE;                    // 64 x 24     3072 B
    float*         sColsum= (float*)(sWo2 + NH * W2_STRIDE);         // 4 x 64      1024 B
    float*         sBias  = sColsum + 4 * NH;                        // 272 floats  1088 B
    __shared__ unsigned sTile;

    const int tid  = threadIdx.x;
    const int lane = tid & 31;
    const int warp = tid >> 5;
    const int m0   = warp * 16;

    // ---- prologue: stage weights via cp.async (overlapped with first obs) ----
    for (int c = tid; c < 512; c += NTHREADS) {       // enc_w 64x64
        int r = c >> 3, ci = c & 7;
        cp16(sWe + r * W_STRIDE + ci * 8, g_enc_w + r * NH + ci * 8);
    }
    for (int c = tid; c < 2048; c += NTHREADS) {      // comm_w 256x64
        int r = c >> 3, ci = c & 7;
        cp16(sWc + r * W_STRIDE + ci * 8, g_comm_w + r * NH + ci * 8);
    }
    for (int c = tid; c < 512; c += NTHREADS) {       // out_w1 64x64
        int r = c >> 3, ci = c & 7;
        cp16(sWo1 + r * W_STRIDE + ci * 8, g_out_w1 + r * NH + ci * 8);
    }
    for (int c = tid; c < 128; c += NTHREADS) {       // out_w2 64x16
        int r = c >> 1, ci = c & 1;
        cp16(sWo2 + r * W2_STRIDE + ci * 8, g_out_w2 + r * NACT + ci * 8);
    }
    if (tid < 64)  sBias[tid]       = enc_b[tid];
    if (tid < 128) sBias[64 + tid]  = comm_b[tid];
    if (tid < 64)  sBias[192 + tid] = out_b1[tid];
    if (tid < 16)  sBias[256 + tid] = out_b2[tid];

    if (tid == 0) sTile = atomicAdd(&g_tile_ctr, 1u);
    __syncthreads();
    unsigned tcur = sTile;
    int par = 0;

    // first tile's obs + avail prefetch
    if (tcur < NTILES) {
        size_t row0 = (size_t)tcur * ROWS;
        for (int c = tid; c < 2048; c += NTHREADS) {
            int r = c >> 4, ci = c & 15;
            cp16(sObs + r * OBS_STRIDE + ci * 4, obs + (row0 + r) * NOBS + ci * 4);
        }
        for (int c = tid; c < 512; c += NTHREADS) {
            int r = c >> 2, ci = c & 3;
            cp16(sAvail + r * NACT + ci * 4, avail + (row0 + r) * NACT + ci * 4);
        }
    }
    cp_commit();

    float acc[8][4];

    while (tcur < NTILES) {
        cp_wait_all();
        __syncthreads();                 // obs/avail (and weights on iter 0) visible

        // ---- convert own rows fp32 -> bf16 into sA cols 0..63 (warp-local) ----
        {
            int r  = m0 + (lane & 15);
            int ch = lane >> 4;          // column half (32 floats)
            const float4*  src = (const float4*)(sObs + r * OBS_STRIDE + ch * 32);
            __nv_bfloat16* dst = sA + r * SA_STRIDE + ch * 32;
#pragma unroll
            for (int i = 0; i < 8; ++i) {
                float4 v = src[i];
                __nv_bfloat162 p0 = __floats2bfloat162_rn(v.x, v.y);
                __nv_bfloat162 p1 = __floats2bfloat162_rn(v.z, v.w);
                uint2 st; st.x = *(uint32_t*)&p0; st.y = *(uint32_t*)&p1;
                *(uint2*)(dst + i * 4) = st;
            }
        }

        // ---- encoder: h = relu(obs @ enc_w + enc_b) (warp-local rows) ----
        warp_gemm<64, 8>(sA, m0, sWe, W_STRIDE, acc, lane);
        store_h(sA, m0, lane, acc, sBias);

        // grab next tile, then sync (h complete; sObs free; sTile visible)
        if (tid == 0) sTile = atomicAdd(&g_tile_ctr, 1u);
        __syncthreads();
        unsigned tnext = sTile;

        // prefetch next tile while we compute this one
        if (tnext < NTILES) {
            size_t row0n = (size_t)tnext * ROWS;
            for (int c = tid; c < 2048; c += NTHREADS) {
                int r = c >> 4, ci = c & 15;
                cp16(sObs + r * OBS_STRIDE + ci * 4, obs + (row0n + r) * NOBS + ci * 4);
            }
            int* sAvN = sAvail + (par ^ 1) * ROWS * NACT;
            for (int c = tid; c < 512; c += NTHREADS) {
                int r = c >> 2, ci = c & 3;
                cp16(sAvN + r * NACT + ci * 4, avail + (row0n + r) * NACT + ci * 4);
            }
        }
        cp_commit();

        // ---- comm rounds ----
#pragma unroll
        for (int rd = 0; rd < NROUNDS; ++rd) {
            if (rd) __syncthreads();     // h from previous round complete
            {   // per-batch column sums over 32 agents
                int b = tid >> 6, c = tid & 63;
                float s = 0.f;
                const __nv_bfloat16* p = sA + (b * NAG) * SA_STRIDE + c;
#pragma unroll
                for (int r = 0; r < NAG; ++r) s += __bfloat162float(p[r * SA_STRIDE]);
                sColsum[(b << 6) + c] = s;
            }
            __syncthreads();
            for (int i = tid; i < ROWS * NH; i += NTHREADS) {
                int row = i >> 6, col = i & 63;
                float hv  = __bfloat162float(sA[row * SA_STRIDE + col]);
                float msg = (sColsum[((row >> 5) << 6) + col] - hv) * (1.0f / 31.0f);
                sA[row * SA_STRIDE + 64 + col] = __float2bfloat16(msg);
            }
            __syncthreads();
            warp_gemm<128, 8>(sA, m0, sWc + rd * 2 * NH * W_STRIDE, W_STRIDE, acc, lane);
            store_h(sA, m0, lane, acc, sBias + 64 + rd * 64);
        }

        // ---- out1 (warp-local) ----
        warp_gemm<64, 8>(sA, m0, sWo1, W_STRIDE, acc, lane);
        store_h(sA, m0, lane, acc, sBias + 192);

        // ---- out2 + mask + store ----
        float acc2[2][4];
        warp_gemm<64, 2>(sA, m0, sWo2, W2_STRIDE, acc2, lane);
        {
            size_t row0 = (size_t)tcur * ROWS;
            const int* sAv = sAvail + par * ROWS * NACT;
            int r    = lane >> 2;
            int colb = (lane & 3) * 2;
#pragma unroll
            for (int nt = 0; nt < 2; ++nt) {
                int col  = nt * 8 + colb;
                float b0 = sBias[256 + col], b1 = sBias[256 + col + 1];
#pragma unroll
                for (int half = 0; half < 2; ++half) {
                    int lrow = m0 + r + half * 8;
                    int2 av = *(const int2*)(sAv + lrow * NACT + col);
                    float q0 = acc2[nt][half * 2 + 0] + b0;
                    float q1 = acc2[nt][half * 2 + 1] + b1;
                    if (av.x == 0) q0 = -1e10f;
                    if (av.y == 0) q1 = -1e10f;
                    *(float2*)(out + (row0 + lrow) * NACT + col) = make_float2(q0, q1);
                }
            }
        }

        par ^= 1;
        tcur = tnext;
    }
}

#define SMEM_BYTES (34816 + 34816 + 16384 + 9216 + 36864 + 9216 + 3072 + 1024 + 1088 + 64)

// ---------------------------------------------------------------------------
extern "C" void kernel_launch(void* const* d_in, const int* in_sizes, int n_in,
                              void* d_out, int out_size) {
    const float* obs    = (const float*)d_in[0];
    const float* enc_w  = (const float*)d_in[1];
    const float* enc_b  = (const float*)d_in[2];
    const float* comm_w = (const float*)d_in[3];
    const float* comm_b = (const float*)d_in[4];
    const float* out_w1 = (const float*)d_in[5];
    const float* out_b1 = (const float*)d_in[6];
    const float* out_w2 = (const float*)d_in[7];
    const float* out_b2 = (const float*)d_in[8];
    const int*   avail  = (const int*)d_in[9];
    float* out = (float*)d_out;

    cudaFuncSetAttribute(commnet_kernel, cudaFuncAttributeMaxDynamicSharedMemorySize, SMEM_BYTES);

    convert_weights_kernel<<<64, 256>>>(enc_w, comm_w, out_w1, out_w2);
    commnet_kernel<<<NCTAS, NTHREADS, SMEM_BYTES>>>(
        obs, enc_b, comm_b, out_b1, out_b2, avail, out);
}

// round 3
// speedup vs baseline: 1.6762x; 1.0222x over previous
#include <cuda_runtime.h>
#include <cuda_bf16.h>
#include <cstdint>

// Problem constants
#define NBATCH   16384
#define NAG      32
#define NOBS     64
#define NH       64
#define NACT     16
#define NROUNDS  2

// Tiling
#define ROWS     128          // rows per tile = 4 batches of 32 agents
#define NTILES   ((NBATCH * NAG) / ROWS)   // 4096
#define NTHREADS 512          // 16 warps; warp pair owns a 16-row stripe, splits N
#define NCTAS    152          // persistent: 1 CTA per SM on GB300

// SMEM strides; pads chosen for conflict-free LDSM
#define SA_STRIDE 136         // activation rows: 128 bf16 cols (h | msg) + 8 pad
#define OBS_STRIDE 68         // fp32 obs staging rows: 64 + 4 pad
#define W_STRIDE  72          // 64-col weight rows + 8 pad
#define W2_STRIDE 24          // 16-col weight rows + 8 pad

// ---------------------------------------------------------------------------
// Globals: bf16 weights (prologue-converted) + persistent work counter
// ---------------------------------------------------------------------------
__device__ __nv_bfloat16 g_enc_w [NOBS * NH];
__device__ __nv_bfloat16 g_comm_w[NROUNDS * 2 * NH * NH];
__device__ __nv_bfloat16 g_out_w1[NH * NH];
__device__ __nv_bfloat16 g_out_w2[NH * NACT];
__device__ unsigned      g_tile_ctr;

__global__ void convert_weights_kernel(const float* __restrict__ enc_w,
                                       const float* __restrict__ comm_w,
                                       const float* __restrict__ out_w1,
                                       const float* __restrict__ out_w2) {
    int i = blockIdx.x * blockDim.x + threadIdx.x;
    if (i == 0) g_tile_ctr = 0;
    if (i < NOBS * NH)                 g_enc_w[i]  = __float2bfloat16(enc_w[i]);
    if (i < NROUNDS * 2 * NH * NH)     g_comm_w[i] = __float2bfloat16(comm_w[i]);
    if (i < NH * NH)                   g_out_w1[i] = __float2bfloat16(out_w1[i]);
    if (i < NH * NACT)                 g_out_w2[i] = __float2bfloat16(out_w2[i]);
}

// ---------------------------------------------------------------------------
// PTX helpers
// ---------------------------------------------------------------------------
__device__ __forceinline__ uint32_t smem_u32(const void* p) {
    return (uint32_t)__cvta_generic_to_shared(p);
}
__device__ __forceinline__ void cp16(void* dst, const void* src) {
    asm volatile("cp.async.cg.shared.global [%0], [%1], 16;"
                 :: "r"(smem_u32(dst)), "l"(src));
}
__device__ __forceinline__ void cp_commit() { asm volatile("cp.async.commit_group;"); }
__device__ __forceinline__ void cp_wait_all() { asm volatile("cp.async.wait_group 0;"); }

// named barrier for a 64-thread warp pair (ids 1..8)
__device__ __forceinline__ void pair_bar(int wp) {
    asm volatile("bar.sync %0, 64;" :: "r"(wp + 1) : "memory");
}

__device__ __forceinline__ void ldsm_x4(uint32_t& r0, uint32_t& r1, uint32_t& r2, uint32_t& r3, uint32_t a) {
    asm volatile("ldmatrix.sync.aligned.m8n8.x4.shared.b16 {%0,%1,%2,%3}, [%4];"
                 : "=r"(r0), "=r"(r1), "=r"(r2), "=r"(r3) : "r"(a));
}
__device__ __forceinline__ void ldsm_x4_t(uint32_t& r0, uint32_t& r1, uint32_t& r2, uint32_t& r3, uint32_t a) {
    asm volatile("ldmatrix.sync.aligned.m8n8.x4.trans.shared.b16 {%0,%1,%2,%3}, [%4];"
                 : "=r"(r0), "=r"(r1), "=r"(r2), "=r"(r3) : "r"(a));
}
__device__ __forceinline__ void mma16816(float* c,
                                         uint32_t a0, uint32_t a1, uint32_t a2, uint32_t a3,
                                         uint32_t b0, uint32_t b1) {
    asm volatile("mma.sync.aligned.m16n8k16.row.col.f32.bf16.bf16.f32 "
                 "{%0,%1,%2,%3}, {%4,%5,%6,%7}, {%8,%9}, {%0,%1,%2,%3};"
                 : "+f"(c[0]), "+f"(c[1]), "+f"(c[2]), "+f"(c[3])
                 : "r"(a0), "r"(a1), "r"(a2), "r"(a3), "r"(b0), "r"(b1));
}

// C[16][8*NT] = A[16][K] @ W[K][8*NT]; sW already offset to this warp's N slice
template <int K, int NT>
__device__ __forceinline__ void warp_gemm(const __nv_bfloat16* sA, int m0,
                                          const __nv_bfloat16* sW, int wstride,
                                          float acc[][4], int lane) {
#pragma unroll
    for (int nt = 0; nt < NT; ++nt) {
        acc[nt][0] = 0.f; acc[nt][1] = 0.f; acc[nt][2] = 0.f; acc[nt][3] = 0.f;
    }
#pragma unroll
    for (int k0 = 0; k0 < K; k0 += 16) {
        uint32_t a0, a1, a2, a3;
        ldsm_x4(a0, a1, a2, a3,
                smem_u32(sA + (m0 + (lane & 15)) * SA_STRIDE + k0 + ((lane >> 4) << 3)));
#pragma unroll
        for (int nt = 0; nt < NT; nt += 2) {
            uint32_t b0, b1, b2, b3;
            ldsm_x4_t(b0, b1, b2, b3,
                      smem_u32(sW + (k0 + (lane & 15)) * wstride + nt * 8 + ((lane >> 4) << 3)));
            mma16816(acc[nt], a0, a1, a2, a3, b0, b1);
            if (nt + 1 < NT) mma16816(acc[nt + 1], a0, a1, a2, a3, b2, b3);
        }
    }
}

// bias + relu + bf16 -> sA[own rows, n0..n0+8*NT)
template <int NT>
__device__ __forceinline__ void store_h(__nv_bfloat16* sA, int m0, int n0, int lane,
                                        float acc[][4], const float* sBias) {
    int row  = m0 + (lane >> 2);
    int colb = (lane & 3) * 2;
#pragma unroll
    for (int nt = 0; nt < NT; ++nt) {
        int col  = n0 + nt * 8 + colb;
        float b0 = sBias[col], b1 = sBias[col + 1];
        float v0 = fmaxf(acc[nt][0] + b0, 0.f);
        float v1 = fmaxf(acc[nt][1] + b1, 0.f);
        float v2 = fmaxf(acc[nt][2] + b0, 0.f);
        float v3 = fmaxf(acc[nt][3] + b1, 0.f);
        *(__nv_bfloat162*)(sA + row * SA_STRIDE + col)       = __floats2bfloat162_rn(v0, v1);
        *(__nv_bfloat162*)(sA + (row + 8) * SA_STRIDE + col) = __floats2bfloat162_rn(v2, v3);
    }
}

// ---------------------------------------------------------------------------
// Persistent fused CommNet kernel: 16 warps, warp pairs split N
// ---------------------------------------------------------------------------
__global__ void __launch_bounds__(NTHREADS, 1)
commnet_kernel(const float* __restrict__ obs,
               const float* __restrict__ enc_b,
               const float* __restrict__ comm_b,
               const float* __restrict__ out_b1,
               const float* __restrict__ out_b2,
               const int*   __restrict__ avail,
               float*       __restrict__ out) {
    extern __shared__ __align__(16) char smem_raw[];
    __nv_bfloat16* sA     = (__nv_bfloat16*)smem_raw;                // 128 x 136   34816 B
    float*         sObs   = (float*)(sA + ROWS * SA_STRIDE);         // 128 x 68    34816 B
    int*           sAvail = (int*)(sObs + ROWS * OBS_STRIDE);        // 2 x 128x16  16384 B
    __nv_bfloat16* sWe    = (__nv_bfloat16*)(sAvail + 2 * ROWS * NACT); // 64 x 72   9216 B
    __nv_bfloat16* sWc    = sWe  + NH * W_STRIDE;                    // 256 x 72   36864 B
    __nv_bfloat16* sWo1   = sWc  + NROUNDS * 2 * NH * W_STRIDE;      // 64 x 72     9216 B
    __nv_bfloat16* sWo2   = sWo1 + NH * W_STRIDE;                    // 64 x 24     3072 B
    float*         sColsum= (float*)(sWo2 + NH * W2_STRIDE);         // 4 x 64      1024 B
    float*         sBias  = sColsum + 4 * NH;                        // 272 floats  1088 B
    __shared__ unsigned sTile;

    const int tid  = threadIdx.x;
    const int lane = tid & 31;
    const int warp = tid >> 5;
    const int wp   = warp >> 1;          // pair id 0..7
    const int nh   = warp & 1;           // N half 0/1
    const int m0   = wp * 16;
    const int n0   = nh * 32;

    // ---- prologue: stage weights via cp.async ----
    for (int c = tid; c < 512; c += NTHREADS) {       // enc_w 64x64
        int r = c >> 3, ci = c & 7;
        cp16(sWe + r * W_STRIDE + ci * 8, g_enc_w + r * NH + ci * 8);
    }
    for (int c = tid; c < 2048; c += NTHREADS) {      // comm_w 256x64
        int r = c >> 3, ci = c & 7;
        cp16(sWc + r * W_STRIDE + ci * 8, g_comm_w + r * NH + ci * 8);
    }
    for (int c = tid; c < 512; c += NTHREADS) {       // out_w1 64x64
        int r = c >> 3, ci = c & 7;
        cp16(sWo1 + r * W_STRIDE + ci * 8, g_out_w1 + r * NH + ci * 8);
    }
    for (int c = tid; c < 128; c += NTHREADS) {       // out_w2 64x16
        int r = c >> 1, ci = c & 1;
        cp16(sWo2 + r * W2_STRIDE + ci * 8, g_out_w2 + r * NACT + ci * 8);
    }
    if (tid < 64)  sBias[tid]       = enc_b[tid];
    if (tid < 128) sBias[64 + tid]  = comm_b[tid];
    if (tid < 64)  sBias[192 + tid] = out_b1[tid];
    if (tid < 16)  sBias[256 + tid] = out_b2[tid];

    if (tid == 0) sTile = atomicAdd(&g_tile_ctr, 1u);
    __syncthreads();
    unsigned tcur = sTile;
    int par = 0;

    // first tile prefetch
    if (tcur < NTILES) {
        size_t row0 = (size_t)tcur * ROWS;
        for (int c = tid; c < 2048; c += NTHREADS) {
            int r = c >> 4, ci = c & 15;
            cp16(sObs + r * OBS_STRIDE + ci * 4, obs + (row0 + r) * NOBS + ci * 4);
        }
        for (int c = tid; c < 512; c += NTHREADS) {
            int r = c >> 2, ci = c & 3;
            cp16(sAvail + r * NACT + ci * 4, avail + (row0 + r) * NACT + ci * 4);
        }
    }
    cp_commit();

    float acc[4][4];

    while (tcur < NTILES) {
        cp_wait_all();
        __syncthreads();                 // obs/avail (and weights on iter 0) visible

        // ---- convert own quadrant fp32 -> bf16 into sA (rows m0..+15, cols n0..+31) ----
        {
            int r  = m0 + (lane & 15);
            int c0 = n0 + ((lane >> 4) << 4);   // 16-col half of the 32-col slice
            const float4*  src = (const float4*)(sObs + r * OBS_STRIDE + c0);
            __nv_bfloat16* dst = sA + r * SA_STRIDE + c0;
#pragma unroll
            for (int i = 0; i < 4; ++i) {
                float4 v = src[i];
                __nv_bfloat162 p0 = __floats2bfloat162_rn(v.x, v.y);
                __nv_bfloat162 p1 = __floats2bfloat162_rn(v.z, v.w);
                uint2 st; st.x = *(uint32_t*)&p0; st.y = *(uint32_t*)&p1;
                *(uint2*)(dst + i * 4) = st;
            }
        }
        pair_bar(wp);                    // partner's obs columns visible

        // ---- encoder: h = relu(obs @ enc_w + enc_b) ----
        warp_gemm<64, 4>(sA, m0, sWe + n0, W_STRIDE, acc, lane);
        pair_bar(wp);                    // partner done reading obs cols before overwrite
        store_h<4>(sA, m0, n0, lane, acc, sBias);

        // grab next tile, then sync (h complete; sObs free; sTile visible)
        if (tid == 0) sTile = atomicAdd(&g_tile_ctr, 1u);
        __syncthreads();
        unsigned tnext = sTile;

        // prefetch next tile while we compute this one
        if (tnext < NTILES) {
            size_t row0n = (size_t)tnext * ROWS;
            for (int c = tid; c < 2048; c += NTHREADS) {
                int r = c >> 4, ci = c & 15;
                cp16(sObs + r * OBS_STRIDE + ci * 4, obs + (row0n + r) * NOBS + ci * 4);
            }
            int* sAvN = sAvail + (par ^ 1) * ROWS * NACT;
            for (int c = tid; c < 512; c += NTHREADS) {
                int r = c >> 2, ci = c & 3;
                cp16(sAvN + r * NACT + ci * 4, avail + (row0n + r) * NACT + ci * 4);
            }
        }
        cp_commit();

        // ---- comm rounds ----
#pragma unroll
        for (int rd = 0; rd < NROUNDS; ++rd) {
            if (rd) __syncthreads();     // h from previous round complete
            if (tid < 256) {             // per-batch column sums over 32 agents
                int b = tid >> 6, c = tid & 63;
                float s = 0.f;
                const __nv_bfloat16* p = sA + (b * NAG) * SA_STRIDE + c;
#pragma unroll
                for (int r = 0; r < NAG; ++r) s += __bfloat162float(p[r * SA_STRIDE]);
                sColsum[(b << 6) + c] = s;
            }
            __syncthreads();
            for (int i = tid; i < ROWS * NH; i += NTHREADS) {
                int row = i >> 6, col = i & 63;
                float hv  = __bfloat162float(sA[row * SA_STRIDE + col]);
                float msg = (sColsum[((row >> 5) << 6) + col] - hv) * (1.0f / 31.0f);
                sA[row * SA_STRIDE + 64 + col] = __float2bfloat16(msg);
            }
            __syncthreads();
            warp_gemm<128, 4>(sA, m0, sWc + rd * 2 * NH * W_STRIDE + n0, W_STRIDE, acc, lane);
            pair_bar(wp);                // partner done reading [h|msg] before overwrite
            store_h<4>(sA, m0, n0, lane, acc, sBias + 64 + rd * 64);
        }
        pair_bar(wp);                    // pair's h(rd1) complete before out1 reads

        // ---- out1: hid = relu(h @ out_w1 + out_b1) ----
        warp_gemm<64, 4>(sA, m0, sWo1 + n0, W_STRIDE, acc, lane);
        pair_bar(wp);                    // partner done reading h before overwrite
        store_h<4>(sA, m0, n0, lane, acc, sBias + 192);
        pair_bar(wp);                    // pair's hid complete before out2 reads

        // ---- out2: q = hid @ out_w2 + out_b2, mask, store (each warp stores its 8 cols) ----
        float acc2[2][4];
        warp_gemm<64, 2>(sA, m0, sWo2, W2_STRIDE, acc2, lane);
        {
            size_t row0 = (size_t)tcur * ROWS;
            const int* sAv = sAvail + par * ROWS * NACT;
            int r    = lane >> 2;
            int colb = (lane & 3) * 2;
            int col  = nh * 8 + colb;
            float b0 = sBias[256 + col], b1 = sBias[256 + col + 1];
#pragma unroll
            for (int half = 0; half < 2; ++half) {
                int lrow = m0 + r + half * 8;
                int2 av = *(const int2*)(sAv + lrow * NACT + col);
                float q0 = acc2[nh][half * 2 + 0] + b0;
                float q1 = acc2[nh][half * 2 + 1] + b1;
                if (av.x == 0) q0 = -1e10f;
                if (av.y == 0) q1 = -1e10f;
                *(float2*)(out + (row0 + lrow) * NACT + col) = make_float2(q0, q1);
            }
        }

        par ^= 1;
        tcur = tnext;
    }
}

#define SMEM_BYTES (34816 + 34816 + 16384 + 9216 + 36864 + 9216 + 3072 + 1024 + 1088 + 64)

// ---------------------------------------------------------------------------
extern "C" void kernel_launch(void* const* d_in, const int* in_sizes, int n_in,
                              void* d_out, int out_size) {
    const float* obs    = (const float*)d_in[0];
    const float* enc_w  = (const float*)d_in[1];
    const float* enc_b  = (const float*)d_in[2];
    const float* comm_w = (const float*)d_in[3];
    const float* comm_b = (const float*)d_in[4];
    const float* out_w1 = (const float*)d_in[5];
    const float* out_b1 = (const float*)d_in[6];
    const float* out_w2 = (const float*)d_in[7];
    const float* out_b2 = (const float*)d_in[8];
    const int*   avail  = (const int*)d_in[9];
    float* out = (float*)d_out;

    cudaFuncSetAttribute(commnet_kernel, cudaFuncAttributeMaxDynamicSharedMemorySize, SMEM_BYTES);

    convert_weights_kernel<<<64, 256>>>(enc_w, comm_w, out_w1, out_w2);
    commnet_kernel<<<NCTAS, NTHREADS, SMEM_BYTES>>>(
        obs, enc_b, comm_b, out_b1, out_b2, avail, out);
}

// round 4
// speedup vs baseline: 2.6961x; 1.6084x over previous
#include <cuda_runtime.h>
#include <cuda_bf16.h>
#include <cstdint>

// Problem constants
#define NBATCH   16384
#define NAG      32
#define NOBS     64
#define NH       64
#define NACT     16
#define NROUNDS  2

// Tiling
#define ROWS     128          // rows per tile = 4 batches of 32 agents
#define NTILES   ((NBATCH * NAG) / ROWS)   // 4096
#define NTHREADS 256          // 8 warps, each owns a 16-row stripe, full N
#define NCTAS    152          // persistent: 1 CTA per SM

// SMEM strides
#define OBS_STRIDE 72         // fp32 obs rows: 64 + 8 pad -> conflict-free LDS.64 frags
#define W_STRIDE  72          // 64-col bf16 weight rows + 8 pad (conflict-free LDSM)
#define W2_STRIDE 24          // 16-col weight rows + 8 pad

// ---------------------------------------------------------------------------
// Globals: bf16 weights (prologue-converted) + persistent work counter
// ---------------------------------------------------------------------------
__device__ __nv_bfloat16 g_enc_w [NOBS * NH];
__device__ __nv_bfloat16 g_comm_w[NROUNDS * 2 * NH * NH];
__device__ __nv_bfloat16 g_out_w1[NH * NH];
__device__ __nv_bfloat16 g_out_w2[NH * NACT];
__device__ unsigned      g_tile_ctr;

__global__ void convert_weights_kernel(const float* __restrict__ enc_w,
                                       const float* __restrict__ comm_w,
                                       const float* __restrict__ out_w1,
                                       const float* __restrict__ out_w2) {
    int i = blockIdx.x * blockDim.x + threadIdx.x;
    if (i == 0) g_tile_ctr = 0;
    if (i < NOBS * NH)                 g_enc_w[i]  = __float2bfloat16(enc_w[i]);
    if (i < NROUNDS * 2 * NH * NH)     g_comm_w[i] = __float2bfloat16(comm_w[i]);
    if (i < NH * NH)                   g_out_w1[i] = __float2bfloat16(out_w1[i]);
    if (i < NH * NACT)                 g_out_w2[i] = __float2bfloat16(out_w2[i]);
}

// ---------------------------------------------------------------------------
// PTX helpers
// ---------------------------------------------------------------------------
__device__ __forceinline__ uint32_t smem_u32(const void* p) {
    return (uint32_t)__cvta_generic_to_shared(p);
}
__device__ __forceinline__ void cp16(void* dst, const void* src) {
    asm volatile("cp.async.cg.shared.global [%0], [%1], 16;"
                 :: "r"(smem_u32(dst)), "l"(src));
}
__device__ __forceinline__ void cp_commit() { asm volatile("cp.async.commit_group;"); }
__device__ __forceinline__ void cp_wait_all() { asm volatile("cp.async.wait_group 0;"); }

__device__ __forceinline__ void ldsm_x4_t(uint32_t& r0, uint32_t& r1, uint32_t& r2, uint32_t& r3, uint32_t a) {
    asm volatile("ldmatrix.sync.aligned.m8n8.x4.trans.shared.b16 {%0,%1,%2,%3}, [%4];"
                 : "=r"(r0), "=r"(r1), "=r"(r2), "=r"(r3) : "r"(a));
}
__device__ __forceinline__ void mma16816(float* c,
                                         uint32_t a0, uint32_t a1, uint32_t a2, uint32_t a3,
                                         uint32_t b0, uint32_t b1) {
    asm volatile("mma.sync.aligned.m16n8k16.row.col.f32.bf16.bf16.f32 "
                 "{%0,%1,%2,%3}, {%4,%5,%6,%7}, {%8,%9}, {%0,%1,%2,%3};"
                 : "+f"(c[0]), "+f"(c[1]), "+f"(c[2]), "+f"(c[3])
                 : "r"(a0), "r"(a1), "r"(a2), "r"(a3), "r"(b0), "r"(b1));
}

__device__ __forceinline__ uint32_t packbf(float x, float y) {
    __nv_bfloat162 p = __floats2bfloat162_rn(x, y);
    return *(uint32_t*)&p;
}
__device__ __forceinline__ float2 unpackbf(uint32_t v) {
    return __bfloat1622float2(*(__nv_bfloat162*)&v);
}

// One K=16 step: A fragment in registers, B from smem (W row-major [K][cols])
template <int NT>
__device__ __forceinline__ void gemm_ktile(const uint32_t a[4],
                                           const __nv_bfloat16* sWk, int wstride,
                                           float acc[][4], int lane) {
#pragma unroll
    for (int nt = 0; nt < NT; nt += 2) {
        uint32_t b0, b1, b2, b3;
        ldsm_x4_t(b0, b1, b2, b3,
                  smem_u32(sWk + (lane & 15) * wstride + nt * 8 + ((lane >> 4) << 3)));
        mma16816(acc[nt], a[0], a[1], a[2], a[3], b0, b1);
        if (nt + 1 < NT) mma16816(acc[nt + 1], a[0], a[1], a[2], a[3], b2, b3);
    }
}

// bias + relu + pack acc[8][4] (n-tiles of 8 cols) into A-fragments hfrag[4][4] (k-tiles of 16)
__device__ __forceinline__ void pack_h(const float acc[][4], uint32_t hfrag[4][4],
                                       const float* sBias, int c) {
#pragma unroll
    for (int t = 0; t < 4; ++t) {
        float2 bA = *(const float2*)(sBias + 16 * t + 2 * c);
        float2 bB = *(const float2*)(sBias + 16 * t + 8 + 2 * c);
        hfrag[t][0] = packbf(fmaxf(acc[2*t][0] + bA.x, 0.f), fmaxf(acc[2*t][1] + bA.y, 0.f));
        hfrag[t][1] = packbf(fmaxf(acc[2*t][2] + bA.x, 0.f), fmaxf(acc[2*t][3] + bA.y, 0.f));
        hfrag[t][2] = packbf(fmaxf(acc[2*t+1][0] + bB.x, 0.f), fmaxf(acc[2*t+1][1] + bB.y, 0.f));
        hfrag[t][3] = packbf(fmaxf(acc[2*t+1][2] + bB.x, 0.f), fmaxf(acc[2*t+1][3] + bB.y, 0.f));
    }
}

// ---------------------------------------------------------------------------
// Persistent fused CommNet kernel: register-resident activations
// ---------------------------------------------------------------------------
__global__ void __launch_bounds__(NTHREADS, 1)
commnet_kernel(const float* __restrict__ obs,
               const float* __restrict__ enc_b,
               const float* __restrict__ comm_b,
               const float* __restrict__ out_b1,
               const float* __restrict__ out_b2,
               const int*   __restrict__ avail,
               float*       __restrict__ out) {
    extern __shared__ __align__(16) char smem_raw[];
    float*         sObs   = (float*)smem_raw;                        // 128 x 72 fp32   36864 B
    int*           sAvail = (int*)(sObs + ROWS * OBS_STRIDE);        // 2 x 128x16      16384 B
    __nv_bfloat16* sWe    = (__nv_bfloat16*)(sAvail + 2 * ROWS * NACT); // 64 x 72       9216 B
    __nv_bfloat16* sWc    = sWe  + NH * W_STRIDE;                    // 256 x 72        36864 B
    __nv_bfloat16* sWo1   = sWc  + NROUNDS * 2 * NH * W_STRIDE;      // 64 x 72          9216 B
    __nv_bfloat16* sWo2   = sWo1 + NH * W_STRIDE;                    // 64 x 24          3072 B
    float*         sColP  = (float*)(sWo2 + NH * W2_STRIDE);         // 2 rd x 8 w x 64  4096 B
    float*         sBias  = sColP + 2 * 8 * NH;                      // 272 floats       1088 B
    __shared__ unsigned sTile;

    const int tid  = threadIdx.x;
    const int lane = tid & 31;
    const int warp = tid >> 5;
    const int m0   = warp * 16;
    const int c    = lane & 3;           // fragment column group
    const int gr   = lane >> 2;          // fragment row within stripe
    const int pb   = warp & ~1;          // warp-pair base (batch = 2 stripes)

    // ---- prologue: stage weights via cp.async ----
    for (int i = tid; i < 512; i += NTHREADS) {       // enc_w 64x64
        int r = i >> 3, ci = i & 7;
        cp16(sWe + r * W_STRIDE + ci * 8, g_enc_w + r * NH + ci * 8);
    }
    for (int i = tid; i < 2048; i += NTHREADS) {      // comm_w 256x64
        int r = i >> 3, ci = i & 7;
        cp16(sWc + r * W_STRIDE + ci * 8, g_comm_w + r * NH + ci * 8);
    }
    for (int i = tid; i < 512; i += NTHREADS) {       // out_w1 64x64
        int r = i >> 3, ci = i & 7;
        cp16(sWo1 + r * W_STRIDE + ci * 8, g_out_w1 + r * NH + ci * 8);
    }
    for (int i = tid; i < 128; i += NTHREADS) {       // out_w2 64x16
        int r = i >> 1, ci = i & 1;
        cp16(sWo2 + r * W2_STRIDE + ci * 8, g_out_w2 + r * NACT + ci * 8);
    }
    if (tid < 64)  sBias[tid]       = enc_b[tid];
    if (tid < 128) sBias[64 + tid]  = comm_b[tid];
    if (tid < 64)  sBias[192 + tid] = out_b1[tid];
    if (tid < 16)  sBias[256 + tid] = out_b2[tid];

    if (tid == 0) sTile = atomicAdd(&g_tile_ctr, 1u);
    __syncthreads();
    unsigned tcur = sTile;
    int par = 0;

    // first tile prefetch
    if (tcur < NTILES) {
        size_t row0 = (size_t)tcur * ROWS;
        for (int i = tid; i < 2048; i += NTHREADS) {
            int r = i >> 4, ci = i & 15;
            cp16(sObs + r * OBS_STRIDE + ci * 4, obs + (row0 + r) * NOBS + ci * 4);
        }
        for (int i = tid; i < 512; i += NTHREADS) {
            int r = i >> 2, ci = i & 3;
            cp16(sAvail + r * NACT + ci * 4, avail + (row0 + r) * NACT + ci * 4);
        }
    }
    cp_commit();

    float    acc[8][4];
    uint32_t hfrag[4][4];
    uint32_t msgfrag[4][4];

    while (tcur < NTILES) {
        cp_wait_all();
        __syncthreads();                 // obs/avail (and weights on iter 0) visible

        // ---- encoder: h = relu(obs @ enc_w + enc_b); A frags straight from fp32 smem ----
#pragma unroll
        for (int nt = 0; nt < 8; ++nt) { acc[nt][0]=0.f; acc[nt][1]=0.f; acc[nt][2]=0.f; acc[nt][3]=0.f; }
#pragma unroll
        for (int t = 0; t < 4; ++t) {
            const float* base = sObs + (m0 + gr) * OBS_STRIDE + 16 * t + 2 * c;
            uint32_t a[4];
            float2 v0 = *(const float2*)(base);
            float2 v1 = *(const float2*)(base + 8 * OBS_STRIDE);
            float2 v2 = *(const float2*)(base + 8);
            float2 v3 = *(const float2*)(base + 8 * OBS_STRIDE + 8);
            a[0] = packbf(v0.x, v0.y); a[1] = packbf(v1.x, v1.y);
            a[2] = packbf(v2.x, v2.y); a[3] = packbf(v3.x, v3.y);
            gemm_ktile<8>(a, sWe + 16 * t * W_STRIDE, W_STRIDE, acc, lane);
        }
        pack_h(acc, hfrag, sBias, c);

        // grab next tile; sync so all warps are done reading sObs before prefetch
        if (tid == 0) sTile = atomicAdd(&g_tile_ctr, 1u);
        __syncthreads();
        unsigned tnext = sTile;

        if (tnext < NTILES) {
            size_t row0n = (size_t)tnext * ROWS;
            for (int i = tid; i < 2048; i += NTHREADS) {
                int r = i >> 4, ci = i & 15;
                cp16(sObs + r * OBS_STRIDE + ci * 4, obs + (row0n + r) * NOBS + ci * 4);
            }
            int* sAvN = sAvail + (par ^ 1) * ROWS * NACT;
            for (int i = tid; i < 512; i += NTHREADS) {
                int r = i >> 2, ci = i & 3;
                cp16(sAvN + r * NACT + ci * 4, avail + (row0n + r) * NACT + ci * 4);
            }
        }
        cp_commit();

        // ---- comm rounds ----
#pragma unroll
        for (int rd = 0; rd < NROUNDS; ++rd) {
            // per-warp partial column sums over own 16 rows via shuffle tree
            float* myP = sColP + (rd * 8 + warp) * NH;
#pragma unroll
            for (int t = 0; t < 4; ++t) {
                float2 lA = unpackbf(hfrag[t][0]), hA = unpackbf(hfrag[t][1]);
                float sx = lA.x + hA.x, sy = lA.y + hA.y;
                float2 lB = unpackbf(hfrag[t][2]), hB = unpackbf(hfrag[t][3]);
                float ux = lB.x + hB.x, uy = lB.y + hB.y;
#pragma unroll
                for (int m = 4; m < 32; m <<= 1) {
                    sx += __shfl_xor_sync(0xffffffffu, sx, m);
                    sy += __shfl_xor_sync(0xffffffffu, sy, m);
                    ux += __shfl_xor_sync(0xffffffffu, ux, m);
                    uy += __shfl_xor_sync(0xffffffffu, uy, m);
                }
                if (lane < 4) {
                    *(float2*)(myP + 16 * t + 2 * lane)     = make_float2(sx, sy);
                    *(float2*)(myP + 16 * t + 8 + 2 * lane) = make_float2(ux, uy);
                }
            }
            __syncthreads();             // all partials of this round visible

            // msg frags in registers: msg = (batch colsum - h) / 31
            const float* p0 = sColP + (rd * 8 + pb) * NH;
            const float* p1 = sColP + (rd * 8 + pb + 1) * NH;
#pragma unroll
            for (int t = 0; t < 4; ++t) {
                float2 a0 = *(const float2*)(p0 + 16 * t + 2 * c);
                float2 a1 = *(const float2*)(p1 + 16 * t + 2 * c);
                float2 csA = make_float2(a0.x + a1.x, a0.y + a1.y);
                float2 b0 = *(const float2*)(p0 + 16 * t + 8 + 2 * c);
                float2 b1 = *(const float2*)(p1 + 16 * t + 8 + 2 * c);
                float2 csB = make_float2(b0.x + b1.x, b0.y + b1.y);
#pragma unroll
                for (int j = 0; j < 2; ++j) {
                    float2 hv = unpackbf(hfrag[t][j]);
                    msgfrag[t][j] = packbf((csA.x - hv.x) * (1.f/31.f), (csA.y - hv.y) * (1.f/31.f));
                    float2 hu = unpackbf(hfrag[t][2 + j]);
                    msgfrag[t][2 + j] = packbf((csB.x - hu.x) * (1.f/31.f), (csB.y - hu.y) * (1.f/31.f));
                }
            }

            // h = relu([h | msg] @ comm_w[rd] + comm_b[rd])  (A entirely in registers)
            const __nv_bfloat16* Wc = sWc + rd * 2 * NH * W_STRIDE;
#pragma unroll
            for (int nt = 0; nt < 8; ++nt) { acc[nt][0]=0.f; acc[nt][1]=0.f; acc[nt][2]=0.f; acc[nt][3]=0.f; }
#pragma unroll
            for (int t = 0; t < 4; ++t)
                gemm_ktile<8>(hfrag[t], Wc + 16 * t * W_STRIDE, W_STRIDE, acc, lane);
#pragma unroll
            for (int t = 0; t < 4; ++t)
                gemm_ktile<8>(msgfrag[t], Wc + (64 + 16 * t) * W_STRIDE, W_STRIDE, acc, lane);
            pack_h(acc, hfrag, sBias + 64 + rd * 64, c);
        }

        // ---- out1: hid = relu(h @ out_w1 + out_b1) ----
#pragma unroll
        for (int nt = 0; nt < 8; ++nt) { acc[nt][0]=0.f; acc[nt][1]=0.f; acc[nt][2]=0.f; acc[nt][3]=0.f; }
#pragma unroll
        for (int t = 0; t < 4; ++t)
            gemm_ktile<8>(hfrag[t], sWo1 + 16 * t * W_STRIDE, W_STRIDE, acc, lane);
        pack_h(acc, hfrag, sBias + 192, c);

        // ---- out2: q = hid @ out_w2 + out_b2, mask, store ----
        float acc2[2][4];
        acc2[0][0]=0.f; acc2[0][1]=0.f; acc2[0][2]=0.f; acc2[0][3]=0.f;
        acc2[1][0]=0.f; acc2[1][1]=0.f; acc2[1][2]=0.f; acc2[1][3]=0.f;
#pragma unroll
        for (int t = 0; t < 4; ++t)
            gemm_ktile<2>(hfrag[t], sWo2 + 16 * t * W2_STRIDE, W2_STRIDE, acc2, lane);
        {
            size_t row0 = (size_t)tcur * ROWS;
            const int* sAv = sAvail + par * ROWS * NACT;
            int colb = c * 2;
#pragma unroll
            for (int nt = 0; nt < 2; ++nt) {
                int col  = nt * 8 + colb;
                float b0 = sBias[256 + col], b1 = sBias[256 + col + 1];
#pragma unroll
                for (int half = 0; half < 2; ++half) {
                    int lrow = m0 + gr + half * 8;
                    int2 av = *(const int2*)(sAv + lrow * NACT + col);
                    float q0 = acc2[nt][half * 2 + 0] + b0;
                    float q1 = acc2[nt][half * 2 + 1] + b1;
                    if (av.x == 0) q0 = -1e10f;
                    if (av.y == 0) q1 = -1e10f;
                    *(float2*)(out + (row0 + lrow) * NACT + col) = make_float2(q0, q1);
                }
            }
        }

        par ^= 1;
        tcur = tnext;
    }
}

#define SMEM_BYTES (36864 + 16384 + 9216 + 36864 + 9216 + 3072 + 4096 + 1088 + 64)

// ---------------------------------------------------------------------------
extern "C" void kernel_launch(void* const* d_in, const int* in_sizes, int n_in,
                              void* d_out, int out_size) {
    const float* obs    = (const float*)d_in[0];
    const float* enc_w  = (const float*)d_in[1];
    const float* enc_b  = (const float*)d_in[2];
    const float* comm_w = (const float*)d_in[3];
    const float* comm_b = (const float*)d_in[4];
    const float* out_w1 = (const float*)d_in[5];
    const float* out_b1 = (const float*)d_in[6];
    const float* out_w2 = (const float*)d_in[7];
    const float* out_b2 = (const float*)d_in[8];
    const int*   avail  = (const int*)d_in[9];
    float* out = (float*)d_out;

    cudaFuncSetAttribute(commnet_kernel, cudaFuncAttributeMaxDynamicSharedMemorySize, SMEM_BYTES);

    convert_weights_kernel<<<64, 256>>>(enc_w, comm_w, out_w1, out_w2);
    commnet_kernel<<<NCTAS, NTHREADS, SMEM_BYTES>>>(
        obs, enc_b, comm_b, out_b1, out_b2, avail, out);
}

// round 5
// speedup vs baseline: 4.0089x; 1.4869x over previous
#include <cuda_runtime.h>
#include <cuda_bf16.h>
#include <cstdint>

// Problem constants
#define NBATCH   16384
#define NAG      32
#define NOBS     64
#define NH       64
#define NACT     16
#define NROUNDS  2

#define NUNITS   NBATCH       // work unit = one batch (32 agents) per warp
#define NTHREADS 256          // 8 warps
#define NCTAS    152          // persistent: 1 CTA per SM

// SMEM weight strides (bf16 elements); picked so ldsm rows hit distinct 16B banks
#define W_STRIDE  72          // 144B/row: (144/16)%8 = r%8 -> conflict-free
#define W2_STRIDE 24          // 48B/row:  (48/16)%8 = 3r%8 -> conflict-free

// ---------------------------------------------------------------------------
// Globals: bf16 weights (prologue-converted) + persistent work counter
// ---------------------------------------------------------------------------
__device__ __nv_bfloat16 g_enc_w [NOBS * NH];
__device__ __nv_bfloat16 g_comm_w[NROUNDS * 2 * NH * NH];
__device__ __nv_bfloat16 g_out_w1[NH * NH];
__device__ __nv_bfloat16 g_out_w2[NH * NACT];
__device__ unsigned      g_tile_ctr;

__global__ void convert_weights_kernel(const float* __restrict__ enc_w,
                                       const float* __restrict__ comm_w,
                                       const float* __restrict__ out_w1,
                                       const float* __restrict__ out_w2) {
    int i = blockIdx.x * blockDim.x + threadIdx.x;
    if (i == 0) g_tile_ctr = 0;
    if (i < NOBS * NH)                 g_enc_w[i]  = __float2bfloat16(enc_w[i]);
    if (i < NROUNDS * 2 * NH * NH)     g_comm_w[i] = __float2bfloat16(comm_w[i]);
    if (i < NH * NH)                   g_out_w1[i] = __float2bfloat16(out_w1[i]);
    if (i < NH * NACT)                 g_out_w2[i] = __float2bfloat16(out_w2[i]);
}

// ---------------------------------------------------------------------------
// PTX helpers
// ---------------------------------------------------------------------------
__device__ __forceinline__ uint32_t smem_u32(const void* p) {
    return (uint32_t)__cvta_generic_to_shared(p);
}
__device__ __forceinline__ void cp16(void* dst, const void* src) {
    asm volatile("cp.async.cg.shared.global [%0], [%1], 16;"
                 :: "r"(smem_u32(dst)), "l"(src));
}
__device__ __forceinline__ void cp_commit() { asm volatile("cp.async.commit_group;"); }
__device__ __forceinline__ void cp_wait_all() { asm volatile("cp.async.wait_group 0;"); }

__device__ __forceinline__ void ldsm_x4_t(uint32_t& r0, uint32_t& r1, uint32_t& r2, uint32_t& r3, uint32_t a) {
    asm volatile("ldmatrix.sync.aligned.m8n8.x4.trans.shared.b16 {%0,%1,%2,%3}, [%4];"
                 : "=r"(r0), "=r"(r1), "=r"(r2), "=r"(r3) : "r"(a));
}
__device__ __forceinline__ void mma16816(float* c,
                                         uint32_t a0, uint32_t a1, uint32_t a2, uint32_t a3,
                                         uint32_t b0, uint32_t b1) {
    asm volatile("mma.sync.aligned.m16n8k16.row.col.f32.bf16.bf16.f32 "
                 "{%0,%1,%2,%3}, {%4,%5,%6,%7}, {%8,%9}, {%0,%1,%2,%3};"
                 : "+f"(c[0]), "+f"(c[1]), "+f"(c[2]), "+f"(c[3])
                 : "r"(a0), "r"(a1), "r"(a2), "r"(a3), "r"(b0), "r"(b1));
}

__device__ __forceinline__ uint32_t packbf(float x, float y) {
    __nv_bfloat162 p = __floats2bfloat162_rn(x, y);
    return *(uint32_t*)&p;
}
__device__ __forceinline__ float2 unpackbf(uint32_t v) {
    return __bfloat1622float2(*(__nv_bfloat162*)&v);
}

// One K=16 step for BOTH stripes: B loaded once, used by 2 A fragments.
template <int NT>
__device__ __forceinline__ void gemm2_ktile(const uint32_t a0[4], const uint32_t a1[4],
                                            const __nv_bfloat16* sWk, int wstride,
                                            float acc0[][4], float acc1[][4], int lane) {
#pragma unroll
    for (int nt = 0; nt < NT; nt += 2) {
        uint32_t b0, b1, b2, b3;
        ldsm_x4_t(b0, b1, b2, b3,
                  smem_u32(sWk + (lane & 15) * wstride + nt * 8 + ((lane >> 4) << 3)));
        mma16816(acc0[nt], a0[0], a0[1], a0[2], a0[3], b0, b1);
        mma16816(acc1[nt], a1[0], a1[1], a1[2], a1[3], b0, b1);
        if (nt + 1 < NT) {
            mma16816(acc0[nt + 1], a0[0], a0[1], a0[2], a0[3], b2, b3);
            mma16816(acc1[nt + 1], a1[0], a1[1], a1[2], a1[3], b2, b3);
        }
    }
}

// bias + relu + pack acc[8][4] into A-fragments hfrag[4][4]
__device__ __forceinline__ void pack_h(const float acc[][4], uint32_t hfrag[][4],
                                       const float* sBias, int c) {
#pragma unroll
    for (int t = 0; t < 4; ++t) {
        float2 bA = *(const float2*)(sBias + 16 * t + 2 * c);
        float2 bB = *(const float2*)(sBias + 16 * t + 8 + 2 * c);
        hfrag[t][0] = packbf(fmaxf(acc[2*t][0] + bA.x, 0.f), fmaxf(acc[2*t][1] + bA.y, 0.f));
        hfrag[t][1] = packbf(fmaxf(acc[2*t][2] + bA.x, 0.f), fmaxf(acc[2*t][3] + bA.y, 0.f));
        hfrag[t][2] = packbf(fmaxf(acc[2*t+1][0] + bB.x, 0.f), fmaxf(acc[2*t+1][1] + bB.y, 0.f));
        hfrag[t][3] = packbf(fmaxf(acc[2*t+1][2] + bB.x, 0.f), fmaxf(acc[2*t+1][3] + bB.y, 0.f));
    }
}

// load obs A-fragments for one batch straight from GMEM (sector-aligned LDG.64)
__device__ __forceinline__ void load_obs_frags(const float* __restrict__ obs,
                                               unsigned b, int gr, int c,
                                               uint32_t ofrag[2][4][4]) {
    const float* base0 = obs + ((size_t)b * NAG) * NOBS;
#pragma unroll
    for (int s = 0; s < 2; ++s) {
        const float* rbase = base0 + (16 * s + gr) * NOBS + 2 * c;
#pragma unroll
        for (int t = 0; t < 4; ++t) {
            const float* p = rbase + 16 * t;
            float2 v0 = __ldg((const float2*)(p));
            float2 v1 = __ldg((const float2*)(p + 8 * NOBS));
            float2 v2 = __ldg((const float2*)(p + 8));
            float2 v3 = __ldg((const float2*)(p + 8 * NOBS + 8));
            ofrag[s][t][0] = packbf(v0.x, v0.y);
            ofrag[s][t][1] = packbf(v1.x, v1.y);
            ofrag[s][t][2] = packbf(v2.x, v2.y);
            ofrag[s][t][3] = packbf(v3.x, v3.y);
        }
    }
}

// ---------------------------------------------------------------------------
// Persistent warp-autonomous CommNet kernel: 1 warp = 1 batch, zero steady-state barriers
// ---------------------------------------------------------------------------
__global__ void __launch_bounds__(NTHREADS, 1)
commnet_kernel(const float* __restrict__ obs,
               const float* __restrict__ enc_b,
               const float* __restrict__ comm_b,
               const float* __restrict__ out_b1,
               const float* __restrict__ out_b2,
               const int*   __restrict__ avail,
               float*       __restrict__ out) {
    extern __shared__ __align__(16) char smem_raw[];
    __nv_bfloat16* sWe  = (__nv_bfloat16*)smem_raw;                  // 64  x 72   9216 B
    __nv_bfloat16* sWc  = sWe  + NH * W_STRIDE;                      // 256 x 72  36864 B
    __nv_bfloat16* sWo1 = sWc  + NROUNDS * 2 * NH * W_STRIDE;        // 64  x 72   9216 B
    __nv_bfloat16* sWo2 = sWo1 + NH * W_STRIDE;                      // 64  x 24   3072 B
    float*         sBias= (float*)(sWo2 + NH * W2_STRIDE);           // 272 floats 1088 B

    const int tid  = threadIdx.x;
    const int lane = tid & 31;
    const int c    = lane & 3;           // fragment column group
    const int gr   = lane >> 2;          // fragment row within stripe

    // ---- prologue: stage weights via cp.async, biases via LDS ----
    for (int i = tid; i < 512; i += NTHREADS) {       // enc_w 64x64
        int r = i >> 3, ci = i & 7;
        cp16(sWe + r * W_STRIDE + ci * 8, g_enc_w + r * NH + ci * 8);
    }
    for (int i = tid; i < 2048; i += NTHREADS) {      // comm_w 256x64
        int r = i >> 3, ci = i & 7;
        cp16(sWc + r * W_STRIDE + ci * 8, g_comm_w + r * NH + ci * 8);
    }
    for (int i = tid; i < 512; i += NTHREADS) {       // out_w1 64x64
        int r = i >> 3, ci = i & 7;
        cp16(sWo1 + r * W_STRIDE + ci * 8, g_out_w1 + r * NH + ci * 8);
    }
    for (int i = tid; i < 128; i += NTHREADS) {       // out_w2 64x16
        int r = i >> 1, ci = i & 1;
        cp16(sWo2 + r * W2_STRIDE + ci * 8, g_out_w2 + r * NACT + ci * 8);
    }
    cp_commit();
    if (tid < 64)  sBias[tid]       = enc_b[tid];
    if (tid < 128) sBias[64 + tid]  = comm_b[tid];
    if (tid < 64)  sBias[192 + tid] = out_b1[tid];
    if (tid < 16)  sBias[256 + tid] = out_b2[tid];
    cp_wait_all();
    __syncthreads();                     // weights + biases visible to all warps

    // ---- per-warp work loop ----
    unsigned b;
    if (lane == 0) b = atomicAdd(&g_tile_ctr, 1u);
    b = __shfl_sync(0xffffffffu, b, 0);

    float    acc[2][8][4];
    uint32_t ofrag[2][4][4];             // obs A-fragments (prefetched)
    uint32_t hfrag[2][4][4];

    if (b < NUNITS) load_obs_frags(obs, b, gr, c, ofrag);

    while (b < NUNITS) {
        const size_t row0 = (size_t)b * NAG;

        // current batch's avail -> registers (completes long before epilogue)
        int2 av[2][2][2];
#pragma unroll
        for (int s = 0; s < 2; ++s)
#pragma unroll
            for (int half = 0; half < 2; ++half) {
                size_t grow = row0 + 16 * s + gr + 8 * half;
#pragma unroll
                for (int nt = 0; nt < 2; ++nt)
                    av[s][nt][half] = __ldg((const int2*)(avail + grow * NACT + nt * 8 + 2 * c));
            }

        // ---- encoder: h = relu(obs @ enc_w + enc_b) ----
#pragma unroll
        for (int s = 0; s < 2; ++s)
#pragma unroll
            for (int nt = 0; nt < 8; ++nt) {
                acc[s][nt][0]=0.f; acc[s][nt][1]=0.f; acc[s][nt][2]=0.f; acc[s][nt][3]=0.f;
            }
#pragma unroll
        for (int t = 0; t < 4; ++t)
            gemm2_ktile<8>(ofrag[0][t], ofrag[1][t], sWe + 16 * t * W_STRIDE, W_STRIDE,
                           acc[0], acc[1], lane);
        pack_h(acc[0], hfrag[0], sBias, c);
        pack_h(acc[1], hfrag[1], sBias, c);

        // ---- grab next batch, prefetch its obs fragments (covers DRAM latency) ----
        unsigned bn;
        if (lane == 0) bn = atomicAdd(&g_tile_ctr, 1u);
        bn = __shfl_sync(0xffffffffu, bn, 0);
        if (bn < NUNITS) load_obs_frags(obs, bn, gr, c, ofrag);

        // ---- comm rounds (fully in-warp) ----
#pragma unroll
        for (int rd = 0; rd < NROUNDS; ++rd) {
            // column sums over the batch's 32 rows: local adds + shuffle butterfly
            float2 csA[4], csB[4];
#pragma unroll
            for (int t = 0; t < 4; ++t) {
                float2 e00 = unpackbf(hfrag[0][t][0]), e01 = unpackbf(hfrag[0][t][1]);
                float2 e10 = unpackbf(hfrag[1][t][0]), e11 = unpackbf(hfrag[1][t][1]);
                float sx = e00.x + e01.x + e10.x + e11.x;
                float sy = e00.y + e01.y + e10.y + e11.y;
                float2 f00 = unpackbf(hfrag[0][t][2]), f01 = unpackbf(hfrag[0][t][3]);
                float2 f10 = unpackbf(hfrag[1][t][2]), f11 = unpackbf(hfrag[1][t][3]);
                float ux = f00.x + f01.x + f10.x + f11.x;
                float uy = f00.y + f01.y + f10.y + f11.y;
#pragma unroll
                for (int m = 4; m < 32; m <<= 1) {
                    sx += __shfl_xor_sync(0xffffffffu, sx, m);
                    sy += __shfl_xor_sync(0xffffffffu, sy, m);
                    ux += __shfl_xor_sync(0xffffffffu, ux, m);
                    uy += __shfl_xor_sync(0xffffffffu, uy, m);
                }
                csA[t] = make_float2(sx, sy);
                csB[t] = make_float2(ux, uy);
            }

            // h = relu([h | msg] @ comm_w[rd] + comm_b[rd]); msg built on the fly
            const __nv_bfloat16* Wc = sWc + rd * 2 * NH * W_STRIDE;
#pragma unroll
            for (int s = 0; s < 2; ++s)
#pragma unroll
                for (int nt = 0; nt < 8; ++nt) {
                    acc[s][nt][0]=0.f; acc[s][nt][1]=0.f; acc[s][nt][2]=0.f; acc[s][nt][3]=0.f;
                }
#pragma unroll
            for (int t = 0; t < 4; ++t)
                gemm2_ktile<8>(hfrag[0][t], hfrag[1][t], Wc + 16 * t * W_STRIDE, W_STRIDE,
                               acc[0], acc[1], lane);
            const float inv31 = 1.0f / 31.0f;
#pragma unroll
            for (int t = 0; t < 4; ++t) {
                uint32_t m0f[4], m1f[4];
#pragma unroll
                for (int s = 0; s < 2; ++s) {
                    uint32_t* mf = s ? m1f : m0f;
#pragma unroll
                    for (int j = 0; j < 2; ++j) {
                        float2 hv = unpackbf(hfrag[s][t][j]);
                        mf[j]     = packbf((csA[t].x - hv.x) * inv31, (csA[t].y - hv.y) * inv31);
                        float2 hu = unpackbf(hfrag[s][t][2 + j]);
                        mf[2 + j] = packbf((csB[t].x - hu.x) * inv31, (csB[t].y - hu.y) * inv31);
                    }
                }
                gemm2_ktile<8>(m0f, m1f, Wc + (64 + 16 * t) * W_STRIDE, W_STRIDE,
                               acc[0], acc[1], lane);
            }
            pack_h(acc[0], hfrag[0], sBias + 64 + rd * 64, c);
            pack_h(acc[1], hfrag[1], sBias + 64 + rd * 64, c);
        }

        // ---- out1: hid = relu(h @ out_w1 + out_b1) ----
#pragma unroll
        for (int s = 0; s < 2; ++s)
#pragma unroll
            for (int nt = 0; nt < 8; ++nt) {
                acc[s][nt][0]=0.f; acc[s][nt][1]=0.f; acc[s][nt][2]=0.f; acc[s][nt][3]=0.f;
            }
#pragma unroll
        for (int t = 0; t < 4; ++t)
            gemm2_ktile<8>(hfrag[0][t], hfrag[1][t], sWo1 + 16 * t * W_STRIDE, W_STRIDE,
                           acc[0], acc[1], lane);
        pack_h(acc[0], hfrag[0], sBias + 192, c);
        pack_h(acc[1], hfrag[1], sBias + 192, c);

        // ---- out2: q = hid @ out_w2 + out_b2, mask, store ----
        float acc2[2][2][4];
#pragma unroll
        for (int s = 0; s < 2; ++s)
#pragma unroll
            for (int nt = 0; nt < 2; ++nt) {
                acc2[s][nt][0]=0.f; acc2[s][nt][1]=0.f; acc2[s][nt][2]=0.f; acc2[s][nt][3]=0.f;
            }
#pragma unroll
        for (int t = 0; t < 4; ++t)
            gemm2_ktile<2>(hfrag[0][t], hfrag[1][t], sWo2 + 16 * t * W2_STRIDE, W2_STRIDE,
                           acc2[0], acc2[1], lane);
        {
            int colb = 2 * c;
#pragma unroll
            for (int s = 0; s < 2; ++s)
#pragma unroll
                for (int nt = 0; nt < 2; ++nt) {
                    int col  = nt * 8 + colb;
                    float b0 = sBias[256 + col], b1 = sBias[256 + col + 1];
#pragma unroll
                    for (int half = 0; half < 2; ++half) {
                        size_t grow = row0 + 16 * s + gr + 8 * half;
                        int2 a = av[s][nt][half];
                        float q0 = acc2[s][nt][half * 2 + 0] + b0;
                        float q1 = acc2[s][nt][half * 2 + 1] + b1;
                        if (a.x == 0) q0 = -1e10f;
                        if (a.y == 0) q1 = -1e10f;
                        *(float2*)(out + grow * NACT + col) = make_float2(q0, q1);
                    }
                }
        }

        b = bn;
    }
}

#define SMEM_BYTES (9216 + 36864 + 9216 + 3072 + 1088 + 64)

// ---------------------------------------------------------------------------
extern "C" void kernel_launch(void* const* d_in, const int* in_sizes, int n_in,
                              void* d_out, int out_size) {
    const float* obs    = (const float*)d_in[0];
    const float* enc_w  = (const float*)d_in[1];
    const float* enc_b  = (const float*)d_in[2];
    const float* comm_w = (const float*)d_in[3];
    const float* comm_b = (const float*)d_in[4];
    const float* out_w1 = (const float*)d_in[5];
    const float* out_b1 = (const float*)d_in[6];
    const float* out_w2 = (const float*)d_in[7];
    const float* out_b2 = (const float*)d_in[8];
    const int*   avail  = (const int*)d_in[9];
    float* out = (float*)d_out;

    cudaFuncSetAttribute(commnet_kernel, cudaFuncAttributeMaxDynamicSharedMemorySize, SMEM_BYTES);

    convert_weights_kernel<<<64, 256>>>(enc_w, comm_w, out_w1, out_w2);
    commnet_kernel<<<NCTAS, NTHREADS, SMEM_BYTES>>>(
        obs, enc_b, comm_b, out_b1, out_b2, avail, out);
}

// round 6
// speedup vs baseline: 4.3063x; 1.0742x over previous
#include <cuda_runtime.h>
#include <cuda_bf16.h>
#include <cstdint>

// Problem constants
#define NBATCH   16384
#define NAG      32
#define NOBS     64
#define NH       64
#define NACT     16
#define NROUNDS  2

#define NUNITS   NBATCH       // work unit = one batch (32 agents) per warp
#define NTHREADS 256          // 8 warps
#define NCTAS    152          // persistent: 1 CTA per SM

// SMEM weight strides (bf16 elements); picked so ldsm rows hit distinct 16B banks
#define W_STRIDE  72          // 144B/row: conflict-free
#define W2_STRIDE 24          // 48B/row: conflict-free

// ---------------------------------------------------------------------------
// Globals: bf16 weights (prologue-converted/decomposed) + persistent work counter
//   comm decomposition: [h|msg] @ Wc == h @ W1' + cs @ W2'
//   W1' = Wc_top - Wc_bot/31,  W2' = Wc_bot/31,  cs = per-batch column sum of h
// ---------------------------------------------------------------------------
__device__ __nv_bfloat16 g_enc_w  [NOBS * NH];
__device__ __nv_bfloat16 g_comm_w1[NROUNDS * NH * NH];
__device__ __nv_bfloat16 g_comm_w2[NROUNDS * NH * NH];
__device__ __nv_bfloat16 g_out_w1 [NH * NH];
__device__ __nv_bfloat16 g_out_w2 [NH * NACT];
__device__ unsigned      g_tile_ctr;

__global__ void convert_weights_kernel(const float* __restrict__ enc_w,
                                       const float* __restrict__ comm_w,
                                       const float* __restrict__ out_w1,
                                       const float* __restrict__ out_w2) {
    int i = blockIdx.x * blockDim.x + threadIdx.x;
    if (i == 0) g_tile_ctr = 0;
    if (i < NOBS * NH) g_enc_w[i]  = __float2bfloat16(enc_w[i]);
    if (i < NH * NH)   g_out_w1[i] = __float2bfloat16(out_w1[i]);
    if (i < NH * NACT) g_out_w2[i] = __float2bfloat16(out_w2[i]);
    if (i < NROUNDS * NH * NH) {
        int r = i / (NH * NH);
        int k = (i / NH) & (NH - 1);
        int j = i & (NH - 1);
        float top = comm_w[r * 2 * NH * NH + k * NH + j];
        float bot = comm_w[r * 2 * NH * NH + (NH + k) * NH + j];
        g_comm_w1[i] = __float2bfloat16(top - bot * (1.0f / 31.0f));
        g_comm_w2[i] = __float2bfloat16(bot * (1.0f / 31.0f));
    }
}

// ---------------------------------------------------------------------------
// PTX helpers
// ---------------------------------------------------------------------------
__device__ __forceinline__ uint32_t smem_u32(const void* p) {
    return (uint32_t)__cvta_generic_to_shared(p);
}
__device__ __forceinline__ void cp16(void* dst, const void* src) {
    asm volatile("cp.async.cg.shared.global [%0], [%1], 16;"
                 :: "r"(smem_u32(dst)), "l"(src));
}
__device__ __forceinline__ void cp_commit() { asm volatile("cp.async.commit_group;"); }
__device__ __forceinline__ void cp_wait_all() { asm volatile("cp.async.wait_group 0;"); }

__device__ __forceinline__ void ldsm_x4_t(uint32_t& r0, uint32_t& r1, uint32_t& r2, uint32_t& r3, uint32_t a) {
    asm volatile("ldmatrix.sync.aligned.m8n8.x4.trans.shared.b16 {%0,%1,%2,%3}, [%4];"
                 : "=r"(r0), "=r"(r1), "=r"(r2), "=r"(r3) : "r"(a));
}
__device__ __forceinline__ void mma16816(float* c,
                                         uint32_t a0, uint32_t a1, uint32_t a2, uint32_t a3,
                                         uint32_t b0, uint32_t b1) {
    asm volatile("mma.sync.aligned.m16n8k16.row.col.f32.bf16.bf16.f32 "
                 "{%0,%1,%2,%3}, {%4,%5,%6,%7}, {%8,%9}, {%0,%1,%2,%3};"
                 : "+f"(c[0]), "+f"(c[1]), "+f"(c[2]), "+f"(c[3])
                 : "r"(a0), "r"(a1), "r"(a2), "r"(a3), "r"(b0), "r"(b1));
}

__device__ __forceinline__ uint32_t packbf(float x, float y) {
    __nv_bfloat162 p = __floats2bfloat162_rn(x, y);
    return *(uint32_t*)&p;
}
__device__ __forceinline__ float2 unpackbf(uint32_t v) {
    return __bfloat1622float2(*(__nv_bfloat162*)&v);
}

// One K=16 step, single A fragment
template <int NT>
__device__ __forceinline__ void gemm_ktile(const uint32_t a[4],
                                           const __nv_bfloat16* sWk, int wstride,
                                           float acc[][4], int lane) {
#pragma unroll
    for (int nt = 0; nt < NT; nt += 2) {
        uint32_t b0, b1, b2, b3;
        ldsm_x4_t(b0, b1, b2, b3,
                  smem_u32(sWk + (lane & 15) * wstride + nt * 8 + ((lane >> 4) << 3)));
        mma16816(acc[nt], a[0], a[1], a[2], a[3], b0, b1);
        if (nt + 1 < NT) mma16816(acc[nt + 1], a[0], a[1], a[2], a[3], b2, b3);
    }
}

// One K=16 step for BOTH stripes: B loaded once, used by 2 A fragments.
template <int NT>
__device__ __forceinline__ void gemm2_ktile(const uint32_t a0[4], const uint32_t a1[4],
                                            const __nv_bfloat16* sWk, int wstride,
                                            float acc0[][4], float acc1[][4], int lane) {
#pragma unroll
    for (int nt = 0; nt < NT; nt += 2) {
        uint32_t b0, b1, b2, b3;
        ldsm_x4_t(b0, b1, b2, b3,
                  smem_u32(sWk + (lane & 15) * wstride + nt * 8 + ((lane >> 4) << 3)));
        mma16816(acc0[nt], a0[0], a0[1], a0[2], a0[3], b0, b1);
        mma16816(acc1[nt], a1[0], a1[1], a1[2], a1[3], b0, b1);
        if (nt + 1 < NT) {
            mma16816(acc0[nt + 1], a0[0], a0[1], a0[2], a0[3], b2, b3);
            mma16816(acc1[nt + 1], a1[0], a1[1], a1[2], a1[3], b2, b3);
        }
    }
}

// bias + relu + pack acc[8][4] into A-fragments hfrag[4][4]
__device__ __forceinline__ void pack_h(const float acc[][4], uint32_t hfrag[][4],
                                       const float* sBias, int c) {
#pragma unroll
    for (int t = 0; t < 4; ++t) {
        float2 bA = *(const float2*)(sBias + 16 * t + 2 * c);
        float2 bB = *(const float2*)(sBias + 16 * t + 8 + 2 * c);
        hfrag[t][0] = packbf(fmaxf(acc[2*t][0] + bA.x, 0.f), fmaxf(acc[2*t][1] + bA.y, 0.f));
        hfrag[t][1] = packbf(fmaxf(acc[2*t][2] + bA.x, 0.f), fmaxf(acc[2*t][3] + bA.y, 0.f));
        hfrag[t][2] = packbf(fmaxf(acc[2*t+1][0] + bB.x, 0.f), fmaxf(acc[2*t+1][1] + bB.y, 0.f));
        hfrag[t][3] = packbf(fmaxf(acc[2*t+1][2] + bB.x, 0.f), fmaxf(acc[2*t+1][3] + bB.y, 0.f));
    }
}

// load obs A-fragments for one batch straight from GMEM (sector-aligned LDG.64)
__device__ __forceinline__ void load_obs_frags(const float* __restrict__ obs,
                                               unsigned b, int gr, int c,
                                               uint32_t ofrag[2][4][4]) {
    const float* base0 = obs + ((size_t)b * NAG) * NOBS;
#pragma unroll
    for (int s = 0; s < 2; ++s) {
        const float* rbase = base0 + (16 * s + gr) * NOBS + 2 * c;
#pragma unroll
        for (int t = 0; t < 4; ++t) {
            const float* p = rbase + 16 * t;
            float2 v0 = __ldg((const float2*)(p));
            float2 v1 = __ldg((const float2*)(p + 8 * NOBS));
            float2 v2 = __ldg((const float2*)(p + 8));
            float2 v3 = __ldg((const float2*)(p + 8 * NOBS + 8));
            ofrag[s][t][0] = packbf(v0.x, v0.y);
            ofrag[s][t][1] = packbf(v1.x, v1.y);
            ofrag[s][t][2] = packbf(v2.x, v2.y);
            ofrag[s][t][3] = packbf(v3.x, v3.y);
        }
    }
}

// ---------------------------------------------------------------------------
// Persistent warp-autonomous CommNet kernel: 1 warp = 1 batch
// ---------------------------------------------------------------------------
__global__ void __launch_bounds__(NTHREADS, 1)
commnet_kernel(const float* __restrict__ obs,
               const float* __restrict__ enc_b,
               const float* __restrict__ comm_b,
               const float* __restrict__ out_b1,
               const float* __restrict__ out_b2,
               const int*   __restrict__ avail,
               float*       __restrict__ out) {
    extern __shared__ __align__(16) char smem_raw[];
    __nv_bfloat16* sWe  = (__nv_bfloat16*)smem_raw;                  // 64  x 72
    __nv_bfloat16* sWc1 = sWe  + NH * W_STRIDE;                      // 128 x 72 (2 rounds)
    __nv_bfloat16* sWc2 = sWc1 + NROUNDS * NH * W_STRIDE;            // 128 x 72 (2 rounds)
    __nv_bfloat16* sWo1 = sWc2 + NROUNDS * NH * W_STRIDE;            // 64  x 72
    __nv_bfloat16* sWo2 = sWo1 + NH * W_STRIDE;                      // 64  x 24
    float*         sBias= (float*)(sWo2 + NH * W2_STRIDE);           // 272 floats

    const int tid  = threadIdx.x;
    const int lane = tid & 31;
    const int c    = lane & 3;           // fragment column group
    const int gr   = lane >> 2;          // fragment row within stripe

    // ---- prologue: stage weights via cp.async, biases via LDS ----
    for (int i = tid; i < 512; i += NTHREADS) {       // enc_w 64x64
        int r = i >> 3, ci = i & 7;
        cp16(sWe + r * W_STRIDE + ci * 8, g_enc_w + r * NH + ci * 8);
    }
    for (int i = tid; i < 1024; i += NTHREADS) {      // comm_w1 128x64
        int r = i >> 3, ci = i & 7;
        cp16(sWc1 + r * W_STRIDE + ci * 8, g_comm_w1 + r * NH + ci * 8);
    }
    for (int i = tid; i < 1024; i += NTHREADS) {      // comm_w2 128x64
        int r = i >> 3, ci = i & 7;
        cp16(sWc2 + r * W_STRIDE + ci * 8, g_comm_w2 + r * NH + ci * 8);
    }
    for (int i = tid; i < 512; i += NTHREADS) {       // out_w1 64x64
        int r = i >> 3, ci = i & 7;
        cp16(sWo1 + r * W_STRIDE + ci * 8, g_out_w1 + r * NH + ci * 8);
    }
    for (int i = tid; i < 128; i += NTHREADS) {       // out_w2 64x16
        int r = i >> 1, ci = i & 1;
        cp16(sWo2 + r * W2_STRIDE + ci * 8, g_out_w2 + r * NACT + ci * 8);
    }
    cp_commit();
    if (tid < 64)  sBias[tid]       = enc_b[tid];
    if (tid < 128) sBias[64 + tid]  = comm_b[tid];
    if (tid < 64)  sBias[192 + tid] = out_b1[tid];
    if (tid < 16)  sBias[256 + tid] = out_b2[tid];
    cp_wait_all();
    __syncthreads();                     // weights + biases visible to all warps

    // ---- per-warp work loop ----
    unsigned b;
    if (lane == 0) b = atomicAdd(&g_tile_ctr, 1u);
    b = __shfl_sync(0xffffffffu, b, 0);

    float    acc[2][8][4];
    uint32_t ofrag[2][4][4];             // obs A-fragments (prefetched)
    uint32_t hfrag[2][4][4];

    if (b < NUNITS) load_obs_frags(obs, b, gr, c, ofrag);

    while (b < NUNITS) {
        const size_t row0 = (size_t)b * NAG;

        // current batch's avail -> registers (completes long before epilogue)
        int2 av[2][2][2];
#pragma unroll
        for (int s = 0; s < 2; ++s)
#pragma unroll
            for (int half = 0; half < 2; ++half) {
                size_t grow = row0 + 16 * s + gr + 8 * half;
#pragma unroll
                for (int nt = 0; nt < 2; ++nt)
                    av[s][nt][half] = __ldg((const int2*)(avail + grow * NACT + nt * 8 + 2 * c));
            }

        // ---- encoder: h = relu(obs @ enc_w + enc_b) ----
#pragma unroll
        for (int s = 0; s < 2; ++s)
#pragma unroll
            for (int nt = 0; nt < 8; ++nt) {
                acc[s][nt][0]=0.f; acc[s][nt][1]=0.f; acc[s][nt][2]=0.f; acc[s][nt][3]=0.f;
            }
#pragma unroll
        for (int t = 0; t < 4; ++t)
            gemm2_ktile<8>(ofrag[0][t], ofrag[1][t], sWe + 16 * t * W_STRIDE, W_STRIDE,
                           acc[0], acc[1], lane);
        pack_h(acc[0], hfrag[0], sBias, c);
        pack_h(acc[1], hfrag[1], sBias, c);

        // ---- grab next batch, prefetch its obs fragments (covers DRAM latency) ----
        unsigned bn;
        if (lane == 0) bn = atomicAdd(&g_tile_ctr, 1u);
        bn = __shfl_sync(0xffffffffu, bn, 0);
        if (bn < NUNITS) load_obs_frags(obs, bn, gr, c, ofrag);

        // ---- comm rounds (fully in-warp, rank-1 decomposed) ----
#pragma unroll
        for (int rd = 0; rd < NROUNDS; ++rd) {
            // column sums over the batch's 32 rows: local adds + shuffle butterfly
            float2 csA[4], csB[4];
#pragma unroll
            for (int t = 0; t < 4; ++t) {
                float2 e00 = unpackbf(hfrag[0][t][0]), e01 = unpackbf(hfrag[0][t][1]);
                float2 e10 = unpackbf(hfrag[1][t][0]), e11 = unpackbf(hfrag[1][t][1]);
                float sx = (e00.x + e01.x) + (e10.x + e11.x);
                float sy = (e00.y + e01.y) + (e10.y + e11.y);
                float2 f00 = unpackbf(hfrag[0][t][2]), f01 = unpackbf(hfrag[0][t][3]);
                float2 f10 = unpackbf(hfrag[1][t][2]), f11 = unpackbf(hfrag[1][t][3]);
                float ux = (f00.x + f01.x) + (f10.x + f11.x);
                float uy = (f00.y + f01.y) + (f10.y + f11.y);
#pragma unroll
                for (int m = 4; m < 32; m <<= 1) {
                    sx += __shfl_xor_sync(0xffffffffu, sx, m);
                    sy += __shfl_xor_sync(0xffffffffu, sy, m);
                    ux += __shfl_xor_sync(0xffffffffu, ux, m);
                    uy += __shfl_xor_sync(0xffffffffu, uy, m);
                }
                csA[t] = make_float2(sx, sy);
                csB[t] = make_float2(ux, uy);
            }

            const __nv_bfloat16* Wc1 = sWc1 + rd * NH * W_STRIDE;
            const __nv_bfloat16* Wc2 = sWc2 + rd * NH * W_STRIDE;

            // R = cs @ W2' (replicated-A, row-invariant) -> acc[0]
#pragma unroll
            for (int nt = 0; nt < 8; ++nt) {
                acc[0][nt][0]=0.f; acc[0][nt][1]=0.f; acc[0][nt][2]=0.f; acc[0][nt][3]=0.f;
            }
#pragma unroll
            for (int t = 0; t < 4; ++t) {
                uint32_t a[4];
                uint32_t pA = packbf(csA[t].x, csA[t].y);
                uint32_t pB = packbf(csB[t].x, csB[t].y);
                a[0] = pA; a[1] = pA; a[2] = pB; a[3] = pB;
                gemm_ktile<8>(a, Wc2 + 16 * t * W_STRIDE, W_STRIDE, acc[0], lane);
            }
            // both stripes start from R
#pragma unroll
            for (int nt = 0; nt < 8; ++nt) {
                acc[1][nt][0]=acc[0][nt][0]; acc[1][nt][1]=acc[0][nt][1];
                acc[1][nt][2]=acc[0][nt][2]; acc[1][nt][3]=acc[0][nt][3];
            }
            // h @ W1' accumulated into both stripes
#pragma unroll
            for (int t = 0; t < 4; ++t)
                gemm2_ktile<8>(hfrag[0][t], hfrag[1][t], Wc1 + 16 * t * W_STRIDE, W_STRIDE,
                               acc[0], acc[1], lane);
            pack_h(acc[0], hfrag[0], sBias + 64 + rd * 64, c);
            pack_h(acc[1], hfrag[1], sBias + 64 + rd * 64, c);
        }

        // ---- out1: hid = relu(h @ out_w1 + out_b1) ----
#pragma unroll
        for (int s = 0; s < 2; ++s)
#pragma unroll
            for (int nt = 0; nt < 8; ++nt) {
                acc[s][nt][0]=0.f; acc[s][nt][1]=0.f; acc[s][nt][2]=0.f; acc[s][nt][3]=0.f;
            }
#pragma unroll
        for (int t = 0; t < 4; ++t)
            gemm2_ktile<8>(hfrag[0][t], hfrag[1][t], sWo1 + 16 * t * W_STRIDE, W_STRIDE,
                           acc[0], acc[1], lane);
        pack_h(acc[0], hfrag[0], sBias + 192, c);
        pack_h(acc[1], hfrag[1], sBias + 192, c);

        // ---- out2: q = hid @ out_w2 + out_b2, mask, store ----
        float acc2[2][2][4];
#pragma unroll
        for (int s = 0; s < 2; ++s)
#pragma unroll
            for (int nt = 0; nt < 2; ++nt) {
                acc2[s][nt][0]=0.f; acc2[s][nt][1]=0.f; acc2[s][nt][2]=0.f; acc2[s][nt][3]=0.f;
            }
#pragma unroll
        for (int t = 0; t < 4; ++t)
            gemm2_ktile<2>(hfrag[0][t], hfrag[1][t], sWo2 + 16 * t * W2_STRIDE, W2_STRIDE,
                           acc2[0], acc2[1], lane);
        {
            int colb = 2 * c;
#pragma unroll
            for (int s = 0; s < 2; ++s)
#pragma unroll
                for (int nt = 0; nt < 2; ++nt) {
                    int col  = nt * 8 + colb;
                    float b0 = sBias[256 + col], b1 = sBias[256 + col + 1];
#pragma unroll
                    for (int half = 0; half < 2; ++half) {
                        size_t grow = row0 + 16 * s + gr + 8 * half;
                        int2 a = av[s][nt][half];
                        float q0 = acc2[s][nt][half * 2 + 0] + b0;
                        float q1 = acc2[s][nt][half * 2 + 1] + b1;
                        if (a.x == 0) q0 = -1e10f;
                        if (a.y == 0) q1 = -1e10f;
                        *(float2*)(out + grow * NACT + col) = make_float2(q0, q1);
                    }
                }
        }

        b = bn;
    }
}

#define SMEM_BYTES ((64*72 + 2*64*72 + 2*64*72 + 64*72 + 64*24) * 2 + 272 * 4 + 64)

// ---------------------------------------------------------------------------
extern "C" void kernel_launch(void* const* d_in, const int* in_sizes, int n_in,
                              void* d_out, int out_size) {
    const float* obs    = (const float*)d_in[0];
    const float* enc_w  = (const float*)d_in[1];
    const float* enc_b  = (const float*)d_in[2];
    const float* comm_w = (const float*)d_in[3];
    const float* comm_b = (const float*)d_in[4];
    const float* out_w1 = (const float*)d_in[5];
    const float* out_b1 = (const float*)d_in[6];
    const float* out_w2 = (const float*)d_in[7];
    const float* out_b2 = (const float*)d_in[8];
    const int*   avail  = (const int*)d_in[9];
    float* out = (float*)d_out;

    cudaFuncSetAttribute(commnet_kernel, cudaFuncAttributeMaxDynamicSharedMemorySize, SMEM_BYTES);

    convert_weights_kernel<<<64, 256>>>(enc_w, comm_w, out_w1, out_w2);
    commnet_kernel<<<NCTAS, NTHREADS, SMEM_BYTES>>>(
        obs, enc_b, comm_b, out_b1, out_b2, avail, out);
}

// round 7
// speedup vs baseline: 4.3218x; 1.0036x over previous
#include <cuda_runtime.h>
#include <cuda_bf16.h>
#include <cstdint>

// Problem constants
#define NBATCH   16384
#define NAG      32
#define NOBS     64
#define NH       64
#define NACT     16
#define NROUNDS  2

#define NUNITS_U (NBATCH / 2)  // work unit = TWO batches (64 rows) per warp
#define NTHREADS 256           // 8 warps
#define NCTAS    152           // persistent: 1 CTA per SM

// SMEM weight strides (bf16 elements); conflict-free LDSM
#define W_STRIDE  72
#define W2_STRIDE 24

// ---------------------------------------------------------------------------
// Globals: bf16 weights (prologue-converted/decomposed) + persistent work counter
//   comm decomposition: [h|msg] @ Wc == h @ W1' + cs @ W2'
//   W1' = Wc_top - Wc_bot/31,  W2' = Wc_bot/31,  cs = per-batch column sum of h
// ---------------------------------------------------------------------------
__device__ __nv_bfloat16 g_enc_w  [NOBS * NH];
__device__ __nv_bfloat16 g_comm_w1[NROUNDS * NH * NH];
__device__ __nv_bfloat16 g_comm_w2[NROUNDS * NH * NH];
__device__ __nv_bfloat16 g_out_w1 [NH * NH];
__device__ __nv_bfloat16 g_out_w2 [NH * NACT];
__device__ unsigned      g_tile_ctr;

__global__ void convert_weights_kernel(const float* __restrict__ enc_w,
                                       const float* __restrict__ comm_w,
                                       const float* __restrict__ out_w1,
                                       const float* __restrict__ out_w2) {
    int i = blockIdx.x * blockDim.x + threadIdx.x;
    if (i == 0) g_tile_ctr = 0;
    if (i < NOBS * NH) g_enc_w[i]  = __float2bfloat16(enc_w[i]);
    if (i < NH * NH)   g_out_w1[i] = __float2bfloat16(out_w1[i]);
    if (i < NH * NACT) g_out_w2[i] = __float2bfloat16(out_w2[i]);
    if (i < NROUNDS * NH * NH) {
        int r = i / (NH * NH);
        int k = (i / NH) & (NH - 1);
        int j = i & (NH - 1);
        float top = comm_w[r * 2 * NH * NH + k * NH + j];
        float bot = comm_w[r * 2 * NH * NH + (NH + k) * NH + j];
        g_comm_w1[i] = __float2bfloat16(top - bot * (1.0f / 31.0f));
        g_comm_w2[i] = __float2bfloat16(bot * (1.0f / 31.0f));
    }
}

// ---------------------------------------------------------------------------
// PTX helpers
// ---------------------------------------------------------------------------
__device__ __forceinline__ uint32_t smem_u32(const void* p) {
    return (uint32_t)__cvta_generic_to_shared(p);
}
__device__ __forceinline__ void cp16(void* dst, const void* src) {
    asm volatile("cp.async.cg.shared.global [%0], [%1], 16;"
                 :: "r"(smem_u32(dst)), "l"(src));
}
__device__ __forceinline__ void cp_commit() { asm volatile("cp.async.commit_group;"); }
__device__ __forceinline__ void cp_wait_all() { asm volatile("cp.async.wait_group 0;"); }
__device__ __forceinline__ void l2pf(const void* p) {
    asm volatile("prefetch.global.L2 [%0];" :: "l"(p));
}

__device__ __forceinline__ void ldsm_x4_t(uint32_t& r0, uint32_t& r1, uint32_t& r2, uint32_t& r3, uint32_t a) {
    asm volatile("ldmatrix.sync.aligned.m8n8.x4.trans.shared.b16 {%0,%1,%2,%3}, [%4];"
                 : "=r"(r0), "=r"(r1), "=r"(r2), "=r"(r3) : "r"(a));
}
__device__ __forceinline__ void mma16816(float* c,
                                         uint32_t a0, uint32_t a1, uint32_t a2, uint32_t a3,
                                         uint32_t b0, uint32_t b1) {
    asm volatile("mma.sync.aligned.m16n8k16.row.col.f32.bf16.bf16.f32 "
                 "{%0,%1,%2,%3}, {%4,%5,%6,%7}, {%8,%9}, {%0,%1,%2,%3};"
                 : "+f"(c[0]), "+f"(c[1]), "+f"(c[2]), "+f"(c[3])
                 : "r"(a0), "r"(a1), "r"(a2), "r"(a3), "r"(b0), "r"(b1));
}

__device__ __forceinline__ uint32_t packbf(float x, float y) {
    __nv_bfloat162 p = __floats2bfloat162_rn(x, y);
    return *(uint32_t*)&p;
}
__device__ __forceinline__ float2 unpackbf(uint32_t v) {
    return __bfloat1622float2(*(__nv_bfloat162*)&v);
}

// One K=16 step, single A fragment
template <int NT>
__device__ __forceinline__ void gemm_ktile(const uint32_t a[4],
                                           const __nv_bfloat16* sWk, int wstride,
                                           float acc[][4], int lane) {
#pragma unroll
    for (int nt = 0; nt < NT; nt += 2) {
        uint32_t b0, b1, b2, b3;
        ldsm_x4_t(b0, b1, b2, b3,
                  smem_u32(sWk + (lane & 15) * wstride + nt * 8 + ((lane >> 4) << 3)));
        mma16816(acc[nt], a[0], a[1], a[2], a[3], b0, b1);
        if (nt + 1 < NT) mma16816(acc[nt + 1], a[0], a[1], a[2], a[3], b2, b3);
    }
}

// One K=16 step for two stripes: B loaded once, used by 2 A fragments.
template <int NT>
__device__ __forceinline__ void gemm2_ktile(const uint32_t a0[4], const uint32_t a1[4],
                                            const __nv_bfloat16* sWk, int wstride,
                                            float acc0[][4], float acc1[][4], int lane) {
#pragma unroll
    for (int nt = 0; nt < NT; nt += 2) {
        uint32_t b0, b1, b2, b3;
        ldsm_x4_t(b0, b1, b2, b3,
                  smem_u32(sWk + (lane & 15) * wstride + nt * 8 + ((lane >> 4) << 3)));
        mma16816(acc0[nt], a0[0], a0[1], a0[2], a0[3], b0, b1);
        mma16816(acc1[nt], a1[0], a1[1], a1[2], a1[3], b0, b1);
        if (nt + 1 < NT) {
            mma16816(acc0[nt + 1], a0[0], a0[1], a0[2], a0[3], b2, b3);
            mma16816(acc1[nt + 1], a1[0], a1[1], a1[2], a1[3], b2, b3);
        }
    }
}

// bias + relu + pack acc[8][4] into A-fragments hfrag[4][4]
__device__ __forceinline__ void pack_h(const float acc[][4], uint32_t hfrag[][4],
                                       const float* sBias, int c) {
#pragma unroll
    for (int t = 0; t < 4; ++t) {
        float2 bA = *(const float2*)(sBias + 16 * t + 2 * c);
        float2 bB = *(const float2*)(sBias + 16 * t + 8 + 2 * c);
        hfrag[t][0] = packbf(fmaxf(acc[2*t][0] + bA.x, 0.f), fmaxf(acc[2*t][1] + bA.y, 0.f));
        hfrag[t][1] = packbf(fmaxf(acc[2*t][2] + bA.x, 0.f), fmaxf(acc[2*t][3] + bA.y, 0.f));
        hfrag[t][2] = packbf(fmaxf(acc[2*t+1][0] + bB.x, 0.f), fmaxf(acc[2*t+1][1] + bB.y, 0.f));
        hfrag[t][3] = packbf(fmaxf(acc[2*t+1][2] + bB.x, 0.f), fmaxf(acc[2*t+1][3] + bB.y, 0.f));
    }
}

// Coalesced obs A-fragment loader: lanes load contiguous float4 (64B/row),
// pack to bf16, then shfl-redistribute pairs into mma A-fragment layout.
// rbase_row = global row of this stripe's row 0.
__device__ __forceinline__ void enc_frags(const float* __restrict__ obs,
                                          size_t rbase_row, int t,
                                          int lane, int gr, int c, uint32_t a[4]) {
    const float* p0 = obs + (rbase_row + gr) * NOBS + 16 * t + 4 * c;
    float4 F0 = __ldg((const float4*)p0);
    float4 F1 = __ldg((const float4*)(p0 + 8 * NOBS));
    uint32_t p0xy = packbf(F0.x, F0.y), p0zw = packbf(F0.z, F0.w);
    uint32_t p1xy = packbf(F1.x, F1.y), p1zw = packbf(F1.z, F1.w);
    int srcA = (lane & ~3) | (c >> 1);   // owner of low col-pair
    int srcB = srcA + 2;                 // owner of high col-pair
    uint32_t txy, tzw;
    txy = __shfl_sync(0xffffffffu, p0xy, srcA);
    tzw = __shfl_sync(0xffffffffu, p0zw, srcA);
    a[0] = (c & 1) ? tzw : txy;          // row gr,   k 2c..2c+1
    txy = __shfl_sync(0xffffffffu, p1xy, srcA);
    tzw = __shfl_sync(0xffffffffu, p1zw, srcA);
    a[1] = (c & 1) ? tzw : txy;          // row gr+8, k 2c..2c+1
    txy = __shfl_sync(0xffffffffu, p0xy, srcB);
    tzw = __shfl_sync(0xffffffffu, p0zw, srcB);
    a[2] = (c & 1) ? tzw : txy;          // row gr,   k 8+2c..
    txy = __shfl_sync(0xffffffffu, p1xy, srcB);
    tzw = __shfl_sync(0xffffffffu, p1zw, srcB);
    a[3] = (c & 1) ? tzw : txy;          // row gr+8, k 8+2c..
}

// ---------------------------------------------------------------------------
// Persistent warp-autonomous CommNet kernel: 1 warp = 2 batches per unit
// ---------------------------------------------------------------------------
__global__ void __launch_bounds__(NTHREADS, 1)
commnet_kernel(const float* __restrict__ obs,
               const float* __restrict__ enc_b,
               const float* __restrict__ comm_b,
               const float* __restrict__ out_b1,
               const float* __restrict__ out_b2,
               const int*   __restrict__ avail,
               float*       __restrict__ out) {
    extern __shared__ __align__(16) char smem_raw[];
    __nv_bfloat16* sWe  = (__nv_bfloat16*)smem_raw;                  // 64  x 72
    __nv_bfloat16* sWc1 = sWe  + NH * W_STRIDE;                      // 128 x 72 (2 rounds)
    __nv_bfloat16* sWc2 = sWc1 + NROUNDS * NH * W_STRIDE;            // 128 x 72 (2 rounds)
    __nv_bfloat16* sWo1 = sWc2 + NROUNDS * NH * W_STRIDE;            // 64  x 72
    __nv_bfloat16* sWo2 = sWo1 + NH * W_STRIDE;                      // 64  x 24
    float*         sBias= (float*)(sWo2 + NH * W2_STRIDE);           // 272 floats

    const int tid  = threadIdx.x;
    const int lane = tid & 31;
    const int c    = lane & 3;
    const int gr   = lane >> 2;

    // ---- prologue: stage weights via cp.async, biases via LDS ----
    for (int i = tid; i < 512; i += NTHREADS) {
        int r = i >> 3, ci = i & 7;
        cp16(sWe + r * W_STRIDE + ci * 8, g_enc_w + r * NH + ci * 8);
    }
    for (int i = tid; i < 1024; i += NTHREADS) {
        int r = i >> 3, ci = i & 7;
        cp16(sWc1 + r * W_STRIDE + ci * 8, g_comm_w1 + r * NH + ci * 8);
    }
    for (int i = tid; i < 1024; i += NTHREADS) {
        int r = i >> 3, ci = i & 7;
        cp16(sWc2 + r * W_STRIDE + ci * 8, g_comm_w2 + r * NH + ci * 8);
    }
    for (int i = tid; i < 512; i += NTHREADS) {
        int r = i >> 3, ci = i & 7;
        cp16(sWo1 + r * W_STRIDE + ci * 8, g_out_w1 + r * NH + ci * 8);
    }
    for (int i = tid; i < 128; i += NTHREADS) {
        int r = i >> 1, ci = i & 1;
        cp16(sWo2 + r * W2_STRIDE + ci * 8, g_out_w2 + r * NACT + ci * 8);
    }
    cp_commit();
    if (tid < 64)  sBias[tid]       = enc_b[tid];
    if (tid < 128) sBias[64 + tid]  = comm_b[tid];
    if (tid < 64)  sBias[192 + tid] = out_b1[tid];
    if (tid < 16)  sBias[256 + tid] = out_b2[tid];
    cp_wait_all();
    __syncthreads();

    // ---- per-warp unit loop (unit = 2 batches = 64 rows) ----
    unsigned u;
    if (lane == 0) u = atomicAdd(&g_tile_ctr, 1u);
    u = __shfl_sync(0xffffffffu, u, 0);

    uint32_t hfrag[2][2][4][4];          // [batch][stripe][ktile][frag]

    while (u < NUNITS_U) {
        const size_t urow0 = (size_t)u * 64;

        // ---- encoder per batch: h = relu(obs @ enc_w + enc_b) ----
#pragma unroll
        for (int s = 0; s < 2; ++s) {
            float acc[2][8][4];
#pragma unroll
            for (int st = 0; st < 2; ++st)
#pragma unroll
                for (int nt = 0; nt < 8; ++nt) {
                    acc[st][nt][0]=0.f; acc[st][nt][1]=0.f; acc[st][nt][2]=0.f; acc[st][nt][3]=0.f;
                }
#pragma unroll
            for (int t = 0; t < 4; ++t) {
                uint32_t a0f[4], a1f[4];
                enc_frags(obs, urow0 + 32 * s,      t, lane, gr, c, a0f);
                enc_frags(obs, urow0 + 32 * s + 16, t, lane, gr, c, a1f);
                gemm2_ktile<8>(a0f, a1f, sWe + 16 * t * W_STRIDE, W_STRIDE,
                               acc[0], acc[1], lane);
            }
            pack_h(acc[0], hfrag[s][0], sBias, c);
            pack_h(acc[1], hfrag[s][1], sBias, c);
        }

        // ---- grab next unit, prefetch its obs+avail to L2 ----
        unsigned un;
        if (lane == 0) un = atomicAdd(&g_tile_ctr, 1u);
        un = __shfl_sync(0xffffffffu, un, 0);
        if (un < NUNITS_U) {
            const char* ob = (const char*)(obs + (size_t)un * 64 * NOBS);
#pragma unroll
            for (int i = 0; i < 4; ++i) l2pf(ob + lane * 128 + i * 4096);
            l2pf((const char*)(avail + (size_t)un * 64 * NACT) + lane * 128);
        }

        // ---- comm rounds (in-warp, rank-1 M-packed across both batches) ----
#pragma unroll
        for (int rd = 0; rd < NROUNDS; ++rd) {
            // per-batch column sums -> packed bf16 cs fragments
            uint32_t csPA[2][4], csPB[2][4];
#pragma unroll
            for (int s = 0; s < 2; ++s) {
#pragma unroll
                for (int t = 0; t < 4; ++t) {
                    float2 e00 = unpackbf(hfrag[s][0][t][0]), e01 = unpackbf(hfrag[s][0][t][1]);
                    float2 e10 = unpackbf(hfrag[s][1][t][0]), e11 = unpackbf(hfrag[s][1][t][1]);
                    float sx = (e00.x + e01.x) + (e10.x + e11.x);
                    float sy = (e00.y + e01.y) + (e10.y + e11.y);
                    float2 f00 = unpackbf(hfrag[s][0][t][2]), f01 = unpackbf(hfrag[s][0][t][3]);
                    float2 f10 = unpackbf(hfrag[s][1][t][2]), f11 = unpackbf(hfrag[s][1][t][3]);
                    float ux = (f00.x + f01.x) + (f10.x + f11.x);
                    float uy = (f00.y + f01.y) + (f10.y + f11.y);
#pragma unroll
                    for (int m = 4; m < 32; m <<= 1) {
                        sx += __shfl_xor_sync(0xffffffffu, sx, m);
                        sy += __shfl_xor_sync(0xffffffffu, sy, m);
                        ux += __shfl_xor_sync(0xffffffffu, ux, m);
                        uy += __shfl_xor_sync(0xffffffffu, uy, m);
                    }
                    csPA[s][t] = packbf(sx, sy);
                    csPB[s][t] = packbf(ux, uy);
                }
            }

            const __nv_bfloat16* Wc1 = sWc1 + rd * NH * W_STRIDE;
            const __nv_bfloat16* Wc2 = sWc2 + rd * NH * W_STRIDE;

            // R (both batches in ONE gemm): A rows 0-7 = cs_b0, rows 8-15 = cs_b1
            float racc[8][4];
#pragma unroll
            for (int nt = 0; nt < 8; ++nt) {
                racc[nt][0]=0.f; racc[nt][1]=0.f; racc[nt][2]=0.f; racc[nt][3]=0.f;
            }
#pragma unroll
            for (int t = 0; t < 4; ++t) {
                uint32_t a[4];
                a[0] = csPA[0][t];   // row gr   (batch0), k 2c
                a[1] = csPA[1][t];   // row gr+8 (batch1), k 2c
                a[2] = csPB[0][t];   // row gr   (batch0), k 8+2c
                a[3] = csPB[1][t];   // row gr+8 (batch1), k 8+2c
                gemm_ktile<8>(a, Wc2 + 16 * t * W_STRIDE, W_STRIDE, racc, lane);
            }

            // per batch: acc = R_b (replicated rows) + h @ W1'
#pragma unroll
            for (int s = 0; s < 2; ++s) {
                float acc[2][8][4];
#pragma unroll
                for (int nt = 0; nt < 8; ++nt) {
                    float lo = racc[nt][2 * s], hi = racc[nt][2 * s + 1];
#pragma unroll
                    for (int st = 0; st < 2; ++st) {
                        acc[st][nt][0] = lo; acc[st][nt][1] = hi;
                        acc[st][nt][2] = lo; acc[st][nt][3] = hi;
                    }
                }
#pragma unroll
                for (int t = 0; t < 4; ++t)
                    gemm2_ktile<8>(hfrag[s][0][t], hfrag[s][1][t],
                                   Wc1 + 16 * t * W_STRIDE, W_STRIDE,
                                   acc[0], acc[1], lane);
                pack_h(acc[0], hfrag[s][0], sBias + 64 + rd * 64, c);
                pack_h(acc[1], hfrag[s][1], sBias + 64 + rd * 64, c);
            }
        }

        // ---- out1 per batch: hid = relu(h @ out_w1 + out_b1) ----
#pragma unroll
        for (int s = 0; s < 2; ++s) {
            float acc[2][8][4];
#pragma unroll
            for (int st = 0; st < 2; ++st)
#pragma unroll
                for (int nt = 0; nt < 8; ++nt) {
                    acc[st][nt][0]=0.f; acc[st][nt][1]=0.f; acc[st][nt][2]=0.f; acc[st][nt][3]=0.f;
                }
#pragma unroll
            for (int t = 0; t < 4; ++t)
                gemm2_ktile<8>(hfrag[s][0][t], hfrag[s][1][t],
                               sWo1 + 16 * t * W_STRIDE, W_STRIDE,
                               acc[0], acc[1], lane);
            pack_h(acc[0], hfrag[s][0], sBias + 192, c);
            pack_h(acc[1], hfrag[s][1], sBias + 192, c);
        }

        // ---- out2 shared across all 4 stripes: one B-ldsm feeds 8 MMAs ----
        float acc2[4][2][4];
#pragma unroll
        for (int s2 = 0; s2 < 4; ++s2)
#pragma unroll
            for (int nt = 0; nt < 2; ++nt) {
                acc2[s2][nt][0]=0.f; acc2[s2][nt][1]=0.f; acc2[s2][nt][2]=0.f; acc2[s2][nt][3]=0.f;
            }
#pragma unroll
        for (int t = 0; t < 4; ++t) {
            uint32_t b0, b1, b2, b3;
            ldsm_x4_t(b0, b1, b2, b3,
                      smem_u32(sWo2 + (16 * t + (lane & 15)) * W2_STRIDE + ((lane >> 4) << 3)));
#pragma unroll
            for (int s2 = 0; s2 < 4; ++s2) {
                const uint32_t* A = hfrag[s2 >> 1][s2 & 1][t];
                mma16816(acc2[s2][0], A[0], A[1], A[2], A[3], b0, b1);
                mma16816(acc2[s2][1], A[0], A[1], A[2], A[3], b2, b3);
            }
        }

        // ---- epilogue: bias + mask + store ----
        {
            int colb = 2 * c;
#pragma unroll
            for (int s2 = 0; s2 < 4; ++s2) {
                size_t rowb = urow0 + (size_t)(s2 >> 1) * 32 + (s2 & 1) * 16;
#pragma unroll
                for (int nt = 0; nt < 2; ++nt) {
                    int col  = nt * 8 + colb;
                    float b0 = sBias[256 + col], b1 = sBias[256 + col + 1];
#pragma unroll
                    for (int half = 0; half < 2; ++half) {
                        size_t grow = rowb + gr + 8 * half;
                        int2 a = __ldg((const int2*)(avail + grow * NACT + col));
                        float q0 = acc2[s2][nt][half * 2 + 0] + b0;
                        float q1 = acc2[s2][nt][half * 2 + 1] + b1;
                        if (a.x == 0) q0 = -1e10f;
                        if (a.y == 0) q1 = -1e10f;
                        *(float2*)(out + grow * NACT + col) = make_float2(q0, q1);
                    }
                }
            }
        }

        u = un;
    }
}

#define SMEM_BYTES ((64*72 + 2*64*72 + 2*64*72 + 64*72 + 64*24) * 2 + 272 * 4 + 64)

// ---------------------------------------------------------------------------
extern "C" void kernel_launch(void* const* d_in, const int* in_sizes, int n_in,
                              void* d_out, int out_size) {
    const float* obs    = (const float*)d_in[0];
    const float* enc_w  = (const float*)d_in[1];
    const float* enc_b  = (const float*)d_in[2];
    const float* comm_w = (const float*)d_in[3];
    const float* comm_b = (const float*)d_in[4];
    const float* out_w1 = (const float*)d_in[5];
    const float* out_b1 = (const float*)d_in[6];
    const float* out_w2 = (const float*)d_in[7];
    const float* out_b2 = (const float*)d_in[8];
    const int*   avail  = (const int*)d_in[9];
    float* out = (float*)d_out;

    cudaFuncSetAttribute(commnet_kernel, cudaFuncAttributeMaxDynamicSharedMemorySize, SMEM_BYTES);

    convert_weights_kernel<<<64, 256>>>(enc_w, comm_w, out_w1, out_w2);
    commnet_kernel<<<NCTAS, NTHREADS, SMEM_BYTES>>>(
        obs, enc_b, comm_b, out_b1, out_b2, avail, out);
}

// round 8
// speedup vs baseline: 4.4042x; 1.0191x over previous
#include <cuda_runtime.h>
#include <cuda_bf16.h>
#include <cstdint>

// Problem constants
#define NBATCH   16384
#define NAG      32
#define NOBS     64
#define NH       64
#define NACT     16
#define NROUNDS  2

#define NUNITS   NBATCH        // work unit = one batch (32 rows) per warp
#define NTHREADS 384           // 12 warps -> 3 per SMSP (regs capped at 170)
#define NCTAS    152           // persistent: 1 CTA per SM

// SMEM weight strides (bf16 elements); conflict-free LDSM
#define W_STRIDE  72
#define W2_STRIDE 24

// ---------------------------------------------------------------------------
// Globals: bf16 weights (prologue-converted/decomposed) + persistent work counter
//   comm decomposition: [h|msg] @ Wc == h @ W1' + cs @ W2'
//   W1' = Wc_top - Wc_bot/31,  W2' = Wc_bot/31,  cs = per-batch column sum of h
// ---------------------------------------------------------------------------
__device__ __nv_bfloat16 g_enc_w  [NOBS * NH];
__device__ __nv_bfloat16 g_comm_w1[NROUNDS * NH * NH];
__device__ __nv_bfloat16 g_comm_w2[NROUNDS * NH * NH];
__device__ __nv_bfloat16 g_out_w1 [NH * NH];
__device__ __nv_bfloat16 g_out_w2 [NH * NACT];
__device__ unsigned      g_tile_ctr;

__global__ void convert_weights_kernel(const float* __restrict__ enc_w,
                                       const float* __restrict__ comm_w,
                                       const float* __restrict__ out_w1,
                                       const float* __restrict__ out_w2) {
    int i = blockIdx.x * blockDim.x + threadIdx.x;
    if (i == 0) g_tile_ctr = 0;
    if (i < NOBS * NH) g_enc_w[i]  = __float2bfloat16(enc_w[i]);
    if (i < NH * NH)   g_out_w1[i] = __float2bfloat16(out_w1[i]);
    if (i < NH * NACT) g_out_w2[i] = __float2bfloat16(out_w2[i]);
    if (i < NROUNDS * NH * NH) {
        int r = i / (NH * NH);
        int k = (i / NH) & (NH - 1);
        int j = i & (NH - 1);
        float top = comm_w[r * 2 * NH * NH + k * NH + j];
        float bot = comm_w[r * 2 * NH * NH + (NH + k) * NH + j];
        g_comm_w1[i] = __float2bfloat16(top - bot * (1.0f / 31.0f));
        g_comm_w2[i] = __float2bfloat16(bot * (1.0f / 31.0f));
    }
}

// ---------------------------------------------------------------------------
// PTX helpers
// ---------------------------------------------------------------------------
__device__ __forceinline__ uint32_t smem_u32(const void* p) {
    return (uint32_t)__cvta_generic_to_shared(p);
}
__device__ __forceinline__ void cp16(void* dst, const void* src) {
    asm volatile("cp.async.cg.shared.global [%0], [%1], 16;"
                 :: "r"(smem_u32(dst)), "l"(src));
}
__device__ __forceinline__ void cp_commit() { asm volatile("cp.async.commit_group;"); }
__device__ __forceinline__ void cp_wait_all() { asm volatile("cp.async.wait_group 0;"); }
__device__ __forceinline__ void l2pf(const void* p) {
    asm volatile("prefetch.global.L2 [%0];" :: "l"(p));
}

__device__ __forceinline__ void ldsm_x4_t(uint32_t& r0, uint32_t& r1, uint32_t& r2, uint32_t& r3, uint32_t a) {
    asm volatile("ldmatrix.sync.aligned.m8n8.x4.trans.shared.b16 {%0,%1,%2,%3}, [%4];"
                 : "=r"(r0), "=r"(r1), "=r"(r2), "=r"(r3) : "r"(a));
}
__device__ __forceinline__ void mma16816(float* c,
                                         uint32_t a0, uint32_t a1, uint32_t a2, uint32_t a3,
                                         uint32_t b0, uint32_t b1) {
    asm volatile("mma.sync.aligned.m16n8k16.row.col.f32.bf16.bf16.f32 "
                 "{%0,%1,%2,%3}, {%4,%5,%6,%7}, {%8,%9}, {%0,%1,%2,%3};"
                 : "+f"(c[0]), "+f"(c[1]), "+f"(c[2]), "+f"(c[3])
                 : "r"(a0), "r"(a1), "r"(a2), "r"(a3), "r"(b0), "r"(b1));
}

__device__ __forceinline__ uint32_t packbf(float x, float y) {
    __nv_bfloat162 p = __floats2bfloat162_rn(x, y);
    return *(uint32_t*)&p;
}
__device__ __forceinline__ float2 unpackbf(uint32_t v) {
    return __bfloat1622float2(*(__nv_bfloat162*)&v);
}

// One K=16 step, single A fragment
template <int NT>
__device__ __forceinline__ void gemm_ktile(const uint32_t a[4],
                                           const __nv_bfloat16* sWk, int wstride,
                                           float acc[][4], int lane) {
#pragma unroll
    for (int nt = 0; nt < NT; nt += 2) {
        uint32_t b0, b1, b2, b3;
        ldsm_x4_t(b0, b1, b2, b3,
                  smem_u32(sWk + (lane & 15) * wstride + nt * 8 + ((lane >> 4) << 3)));
        mma16816(acc[nt], a[0], a[1], a[2], a[3], b0, b1);
        if (nt + 1 < NT) mma16816(acc[nt + 1], a[0], a[1], a[2], a[3], b2, b3);
    }
}

// One K=16 step for two stripes: B loaded once, used by 2 A fragments.
template <int NT>
__device__ __forceinline__ void gemm2_ktile(const uint32_t a0[4], const uint32_t a1[4],
                                            const __nv_bfloat16* sWk, int wstride,
                                            float acc0[][4], float acc1[][4], int lane) {
#pragma unroll
    for (int nt = 0; nt < NT; nt += 2) {
        uint32_t b0, b1, b2, b3;
        ldsm_x4_t(b0, b1, b2, b3,
                  smem_u32(sWk + (lane & 15) * wstride + nt * 8 + ((lane >> 4) << 3)));
        mma16816(acc0[nt], a0[0], a0[1], a0[2], a0[3], b0, b1);
        mma16816(acc1[nt], a1[0], a1[1], a1[2], a1[3], b0, b1);
        if (nt + 1 < NT) {
            mma16816(acc0[nt + 1], a0[0], a0[1], a0[2], a0[3], b2, b3);
            mma16816(acc1[nt + 1], a1[0], a1[1], a1[2], a1[3], b2, b3);
        }
    }
}

// bias + relu + pack acc[8][4] into A-fragments hfrag[4][4]
__device__ __forceinline__ void pack_h(const float acc[][4], uint32_t hfrag[][4],
                                       const float* sBias, int c) {
#pragma unroll
    for (int t = 0; t < 4; ++t) {
        float2 bA = *(const float2*)(sBias + 16 * t + 2 * c);
        float2 bB = *(const float2*)(sBias + 16 * t + 8 + 2 * c);
        hfrag[t][0] = packbf(fmaxf(acc[2*t][0] + bA.x, 0.f), fmaxf(acc[2*t][1] + bA.y, 0.f));
        hfrag[t][1] = packbf(fmaxf(acc[2*t][2] + bA.x, 0.f), fmaxf(acc[2*t][3] + bA.y, 0.f));
        hfrag[t][2] = packbf(fmaxf(acc[2*t+1][0] + bB.x, 0.f), fmaxf(acc[2*t+1][1] + bB.y, 0.f));
        hfrag[t][3] = packbf(fmaxf(acc[2*t+1][2] + bB.x, 0.f), fmaxf(acc[2*t+1][3] + bB.y, 0.f));
    }
}

// Coalesced obs A-fragment loader: lanes load contiguous float4 (64B/row),
// pack to bf16, then shfl-redistribute pairs into mma A-fragment layout.
__device__ __forceinline__ void enc_frags(const float* __restrict__ obs,
                                          size_t rbase_row, int t,
                                          int lane, int gr, int c, uint32_t a[4]) {
    const float* p0 = obs + (rbase_row + gr) * NOBS + 16 * t + 4 * c;
    float4 F0 = __ldg((const float4*)p0);
    float4 F1 = __ldg((const float4*)(p0 + 8 * NOBS));
    uint32_t p0xy = packbf(F0.x, F0.y), p0zw = packbf(F0.z, F0.w);
    uint32_t p1xy = packbf(F1.x, F1.y), p1zw = packbf(F1.z, F1.w);
    int srcA = (lane & ~3) | (c >> 1);
    int srcB = srcA + 2;
    uint32_t txy, tzw;
    txy = __shfl_sync(0xffffffffu, p0xy, srcA);
    tzw = __shfl_sync(0xffffffffu, p0zw, srcA);
    a[0] = (c & 1) ? tzw : txy;
    txy = __shfl_sync(0xffffffffu, p1xy, srcA);
    tzw = __shfl_sync(0xffffffffu, p1zw, srcA);
    a[1] = (c & 1) ? tzw : txy;
    txy = __shfl_sync(0xffffffffu, p0xy, srcB);
    tzw = __shfl_sync(0xffffffffu, p0zw, srcB);
    a[2] = (c & 1) ? tzw : txy;
    txy = __shfl_sync(0xffffffffu, p1xy, srcB);
    tzw = __shfl_sync(0xffffffffu, p1zw, srcB);
    a[3] = (c & 1) ? tzw : txy;
}

// ---------------------------------------------------------------------------
// Persistent warp-autonomous CommNet kernel: 1 warp = 1 batch, 12 warps/SM
// ---------------------------------------------------------------------------
__global__ void __launch_bounds__(NTHREADS, 1)
commnet_kernel(const float* __restrict__ obs,
               const float* __restrict__ enc_b,
               const float* __restrict__ comm_b,
               const float* __restrict__ out_b1,
               const float* __restrict__ out_b2,
               const int*   __restrict__ avail,
               float*       __restrict__ out) {
    extern __shared__ __align__(16) char smem_raw[];
    __nv_bfloat16* sWe  = (__nv_bfloat16*)smem_raw;                  // 64  x 72
    __nv_bfloat16* sWc1 = sWe  + NH * W_STRIDE;                      // 128 x 72 (2 rounds)
    __nv_bfloat16* sWc2 = sWc1 + NROUNDS * NH * W_STRIDE;            // 128 x 72 (2 rounds)
    __nv_bfloat16* sWo1 = sWc2 + NROUNDS * NH * W_STRIDE;            // 64  x 72
    __nv_bfloat16* sWo2 = sWo1 + NH * W_STRIDE;                      // 64  x 24
    float*         sBias= (float*)(sWo2 + NH * W2_STRIDE);           // 272 floats

    const int tid  = threadIdx.x;
    const int lane = tid & 31;
    const int c    = lane & 3;
    const int gr   = lane >> 2;

    // ---- prologue: stage weights via cp.async, biases via LDS ----
    for (int i = tid; i < 512; i += NTHREADS) {
        int r = i >> 3, ci = i & 7;
        cp16(sWe + r * W_STRIDE + ci * 8, g_enc_w + r * NH + ci * 8);
    }
    for (int i = tid; i < 1024; i += NTHREADS) {
        int r = i >> 3, ci = i & 7;
        cp16(sWc1 + r * W_STRIDE + ci * 8, g_comm_w1 + r * NH + ci * 8);
    }
    for (int i = tid; i < 1024; i += NTHREADS) {
        int r = i >> 3, ci = i & 7;
        cp16(sWc2 + r * W_STRIDE + ci * 8, g_comm_w2 + r * NH + ci * 8);
    }
    for (int i = tid; i < 512; i += NTHREADS) {
        int r = i >> 3, ci = i & 7;
        cp16(sWo1 + r * W_STRIDE + ci * 8, g_out_w1 + r * NH + ci * 8);
    }
    for (int i = tid; i < 128; i += NTHREADS) {
        int r = i >> 1, ci = i & 1;
        cp16(sWo2 + r * W2_STRIDE + ci * 8, g_out_w2 + r * NACT + ci * 8);
    }
    cp_commit();
    if (tid < 64)  sBias[tid]       = enc_b[tid];
    if (tid < 128) sBias[64 + tid]  = comm_b[tid];
    if (tid < 64)  sBias[192 + tid] = out_b1[tid];
    if (tid < 16)  sBias[256 + tid] = out_b2[tid];
    cp_wait_all();
    __syncthreads();

    // ---- per-warp batch loop ----
    unsigned b;
    if (lane == 0) b = atomicAdd(&g_tile_ctr, 1u);
    b = __shfl_sync(0xffffffffu, b, 0);

    uint32_t hfrag[2][4][4];             // [stripe][ktile][frag]

    while (b < NUNITS) {
        const size_t row0 = (size_t)b * NAG;

        // ---- encoder: h = relu(obs @ enc_w + enc_b) ----
        {
            float acc[2][8][4];
#pragma unroll
            for (int st = 0; st < 2; ++st)
#pragma unroll
                for (int nt = 0; nt < 8; ++nt) {
                    acc[st][nt][0]=0.f; acc[st][nt][1]=0.f; acc[st][nt][2]=0.f; acc[st][nt][3]=0.f;
                }
#pragma unroll
            for (int t = 0; t < 4; ++t) {
                uint32_t a0f[4], a1f[4];
                enc_frags(obs, row0,      t, lane, gr, c, a0f);
                enc_frags(obs, row0 + 16, t, lane, gr, c, a1f);
                gemm2_ktile<8>(a0f, a1f, sWe + 16 * t * W_STRIDE, W_STRIDE,
                               acc[0], acc[1], lane);
            }
            pack_h(acc[0], hfrag[0], sBias, c);
            pack_h(acc[1], hfrag[1], sBias, c);
        }

        // ---- grab next batch, prefetch its obs+avail to L2 ----
        unsigned bn;
        if (lane == 0) bn = atomicAdd(&g_tile_ctr, 1u);
        bn = __shfl_sync(0xffffffffu, bn, 0);
        if (bn < NUNITS) {
            const char* ob = (const char*)(obs + (size_t)bn * NAG * NOBS);
#pragma unroll
            for (int i = 0; i < 2; ++i) l2pf(ob + lane * 128 + i * 4096);
            if (lane < 16) l2pf((const char*)(avail + (size_t)bn * NAG * NACT) + lane * 128);
        }

        // ---- comm rounds (in-warp, rank-1 decomposed) ----
#pragma unroll
        for (int rd = 0; rd < NROUNDS; ++rd) {
            // column sums over the batch's 32 rows: local adds + shuffle butterfly
            uint32_t csPA[4], csPB[4];
#pragma unroll
            for (int t = 0; t < 4; ++t) {
                float2 e00 = unpackbf(hfrag[0][t][0]), e01 = unpackbf(hfrag[0][t][1]);
                float2 e10 = unpackbf(hfrag[1][t][0]), e11 = unpackbf(hfrag[1][t][1]);
                float sx = (e00.x + e01.x) + (e10.x + e11.x);
                float sy = (e00.y + e01.y) + (e10.y + e11.y);
                float2 f00 = unpackbf(hfrag[0][t][2]), f01 = unpackbf(hfrag[0][t][3]);
                float2 f10 = unpackbf(hfrag[1][t][2]), f11 = unpackbf(hfrag[1][t][3]);
                float ux = (f00.x + f01.x) + (f10.x + f11.x);
                float uy = (f00.y + f01.y) + (f10.y + f11.y);
#pragma unroll
                for (int m = 4; m < 32; m <<= 1) {
                    sx += __shfl_xor_sync(0xffffffffu, sx, m);
                    sy += __shfl_xor_sync(0xffffffffu, sy, m);
                    ux += __shfl_xor_sync(0xffffffffu, ux, m);
                    uy += __shfl_xor_sync(0xffffffffu, uy, m);
                }
                csPA[t] = packbf(sx, sy);
                csPB[t] = packbf(ux, uy);
            }

            const __nv_bfloat16* Wc1 = sWc1 + rd * NH * W_STRIDE;
            const __nv_bfloat16* Wc2 = sWc2 + rd * NH * W_STRIDE;

            float acc[2][8][4];
            // R = cs @ W2' (replicated-A, row-invariant) -> acc[0]
#pragma unroll
            for (int nt = 0; nt < 8; ++nt) {
                acc[0][nt][0]=0.f; acc[0][nt][1]=0.f; acc[0][nt][2]=0.f; acc[0][nt][3]=0.f;
            }
#pragma unroll
            for (int t = 0; t < 4; ++t) {
                uint32_t a[4];
                a[0] = csPA[t]; a[1] = csPA[t];
                a[2] = csPB[t]; a[3] = csPB[t];
                gemm_ktile<8>(a, Wc2 + 16 * t * W_STRIDE, W_STRIDE, acc[0], lane);
            }
            // both stripes start from R
#pragma unroll
            for (int nt = 0; nt < 8; ++nt) {
                acc[1][nt][0]=acc[0][nt][0]; acc[1][nt][1]=acc[0][nt][1];
                acc[1][nt][2]=acc[0][nt][2]; acc[1][nt][3]=acc[0][nt][3];
            }
            // h @ W1' accumulated into both stripes
#pragma unroll
            for (int t = 0; t < 4; ++t)
                gemm2_ktile<8>(hfrag[0][t], hfrag[1][t], Wc1 + 16 * t * W_STRIDE, W_STRIDE,
                               acc[0], acc[1], lane);
            pack_h(acc[0], hfrag[0], sBias + 64 + rd * 64, c);
            pack_h(acc[1], hfrag[1], sBias + 64 + rd * 64, c);
        }

        // ---- out1: hid = relu(h @ out_w1 + out_b1) ----
        {
            float acc[2][8][4];
#pragma unroll
            for (int st = 0; st < 2; ++st)
#pragma unroll
                for (int nt = 0; nt < 8; ++nt) {
                    acc[st][nt][0]=0.f; acc[st][nt][1]=0.f; acc[st][nt][2]=0.f; acc[st][nt][3]=0.f;
                }
#pragma unroll
            for (int t = 0; t < 4; ++t)
                gemm2_ktile<8>(hfrag[0][t], hfrag[1][t], sWo1 + 16 * t * W_STRIDE, W_STRIDE,
                               acc[0], acc[1], lane);
            pack_h(acc[0], hfrag[0], sBias + 192, c);
            pack_h(acc[1], hfrag[1], sBias + 192, c);
        }

        // ---- out2 shared across both stripes: one B-ldsm feeds 4 MMAs ----
        float acc2[2][2][4];
#pragma unroll
        for (int st = 0; st < 2; ++st)
#pragma unroll
            for (int nt = 0; nt < 2; ++nt) {
                acc2[st][nt][0]=0.f; acc2[st][nt][1]=0.f; acc2[st][nt][2]=0.f; acc2[st][nt][3]=0.f;
            }
#pragma unroll
        for (int t = 0; t < 4; ++t) {
            uint32_t b0, b1, b2, b3;
            ldsm_x4_t(b0, b1, b2, b3,
                      smem_u32(sWo2 + (16 * t + (lane & 15)) * W2_STRIDE + ((lane >> 4) << 3)));
#pragma unroll
            for (int st = 0; st < 2; ++st) {
                const uint32_t* A = hfrag[st][t];
                mma16816(acc2[st][0], A[0], A[1], A[2], A[3], b0, b1);
                mma16816(acc2[st][1], A[0], A[1], A[2], A[3], b2, b3);
            }
        }

        // ---- epilogue: bias + mask + store ----
        {
            int colb = 2 * c;
#pragma unroll
            for (int st = 0; st < 2; ++st) {
                size_t rowb = row0 + st * 16;
#pragma unroll
                for (int nt = 0; nt < 2; ++nt) {
                    int col  = nt * 8 + colb;
                    float b0 = sBias[256 + col], b1 = sBias[256 + col + 1];
#pragma unroll
                    for (int half = 0; half < 2; ++half) {
                        size_t grow = rowb + gr + 8 * half;
                        int2 a = __ldg((const int2*)(avail + grow * NACT + col));
                        float q0 = acc2[st][nt][half * 2 + 0] + b0;
                        float q1 = acc2[st][nt][half * 2 + 1] + b1;
                        if (a.x == 0) q0 = -1e10f;
                        if (a.y == 0) q1 = -1e10f;
                        *(float2*)(out + grow * NACT + col) = make_float2(q0, q1);
                    }
                }
            }
        }

        b = bn;
    }
}

#define SMEM_BYTES ((64*72 + 2*64*72 + 2*64*72 + 64*72 + 64*24) * 2 + 272 * 4 + 64)

// ---------------------------------------------------------------------------
extern "C" void kernel_launch(void* const* d_in, const int* in_sizes, int n_in,
                              void* d_out, int out_size) {
    const float* obs    = (const float*)d_in[0];
    const float* enc_w  = (const float*)d_in[1];
    const float* enc_b  = (const float*)d_in[2];
    const float* comm_w = (const float*)d_in[3];
    const float* comm_b = (const float*)d_in[4];
    const float* out_w1 = (const float*)d_in[5];
    const float* out_b1 = (const float*)d_in[6];
    const float* out_w2 = (const float*)d_in[7];
    const float* out_b2 = (const float*)d_in[8];
    const int*   avail  = (const int*)d_in[9];
    float* out = (float*)d_out;

    cudaFuncSetAttribute(commnet_kernel, cudaFuncAttributeMaxDynamicSharedMemorySize, SMEM_BYTES);

    convert_weights_kernel<<<64, 256>>>(enc_w, comm_w, out_w1, out_w2);
    commnet_kernel<<<NCTAS, NTHREADS, SMEM_BYTES>>>(
        obs, enc_b, comm_b, out_b1, out_b2, avail, out);
}